// round 2
// baseline (speedup 1.0000x reference)
#include <cuda_runtime.h>
#include <cstdint>
#include <cstddef>

// Problem constants (validated against in_sizes at launch)
#define N_D   128          // node feature dim
#define N_H   256          // hidden dim
#define N_CAT 256          // 2*D
#define BN_EPS 1e-5f

// ---------------------------------------------------------------------------
// Scratch (static __device__ globals; no allocation in kernel_launch)
// ---------------------------------------------------------------------------
__device__ float g_agg[(size_t)100000 * N_D];     // 51.2 MB  aggregated messages
__device__ float g_h  [(size_t)100000 * N_H];     // 102.4 MB hidden activations
__device__ float g_stats[4 * 256];                // [0:256) sum_cat [256:512) sq_cat [512:768) sum_h [768:1024) sq_h
__device__ float g_scale1[N_CAT], g_shift1[N_CAT];
__device__ float g_scale2[N_H],  g_shift2[N_H];
__device__ float g_W1p[N_CAT * N_H];              // BN1-folded W1
__device__ float g_b1p[N_H];                      // BN1-folded b1

// ---------------------------------------------------------------------------
// Zero scratch (agg + ALL stats)
// ---------------------------------------------------------------------------
__global__ void k_zero(size_t n4) {
    size_t i = (size_t)blockIdx.x * blockDim.x + threadIdx.x;
    size_t stride = (size_t)gridDim.x * blockDim.x;
    float4* p = reinterpret_cast<float4*>(g_agg);
    float4 z = make_float4(0.f, 0.f, 0.f, 0.f);
    for (; i < n4; i += stride) p[i] = z;
    if (blockIdx.x == 0) {
        for (int j = threadIdx.x; j < 4 * 256; j += blockDim.x) g_stats[j] = 0.f;
    }
}

// ---------------------------------------------------------------------------
// SpMM: warp per edge. agg[rows[e]] += vals[e] * input[cols[e]]
// ---------------------------------------------------------------------------
__global__ void k_spmm(const float* __restrict__ x,
                       const int* __restrict__ rows,
                       const int* __restrict__ cols,
                       const float* __restrict__ vals,
                       int E) {
    int widx = (int)(((size_t)blockIdx.x * blockDim.x + threadIdx.x) >> 5);
    int lane = threadIdx.x & 31;
    if (widx >= E) return;
    int r = rows[widx];
    int c = cols[widx];
    float v = vals[widx];
    float4 m = reinterpret_cast<const float4*>(x + (size_t)c * N_D)[lane];
    float* dst = g_agg + (size_t)r * N_D + lane * 4;
    atomicAdd(dst + 0, v * m.x);
    atomicAdd(dst + 1, v * m.y);
    atomicAdd(dst + 2, v * m.z);
    atomicAdd(dst + 3, v * m.w);
}

// ---------------------------------------------------------------------------
// Column stats of x_cat = [input | g_agg]  (256 cols over n rows)
// ---------------------------------------------------------------------------
__global__ void k_stats_cat(const float* __restrict__ x, int n) {
    int t = threadIdx.x;                                  // 0..255 = column
    const float* base = (t < N_D) ? (x + t) : (g_agg + (t - N_D));
    float s = 0.f, sq = 0.f;
    for (int r = blockIdx.x; r < n; r += gridDim.x) {
        float v = base[(size_t)r * N_D];
        s += v;
        sq += v * v;
    }
    atomicAdd(&g_stats[t], s);
    atomicAdd(&g_stats[256 + t], sq);
}

// Column stats of g_h (256 cols)
__global__ void k_stats_h(int n) {
    int t = threadIdx.x;
    float s = 0.f, sq = 0.f;
    for (int r = blockIdx.x; r < n; r += gridDim.x) {
        float v = g_h[(size_t)r * N_H + t];
        s += v;
        sq += v * v;
    }
    atomicAdd(&g_stats[512 + t], s);
    atomicAdd(&g_stats[768 + t], sq);
}

// ---------------------------------------------------------------------------
// BN param prep: scale/shift from batch stats
// ---------------------------------------------------------------------------
__global__ void k_bn1_prep(const float* __restrict__ gamma,
                           const float* __restrict__ beta, float n_inv) {
    int t = threadIdx.x;
    float mean = g_stats[t] * n_inv;
    float var  = g_stats[256 + t] * n_inv - mean * mean;
    float sc   = gamma[t] * rsqrtf(var + BN_EPS);
    g_scale1[t] = sc;
    g_shift1[t] = beta[t] - mean * sc;
}

__global__ void k_bn2_prep(const float* __restrict__ gamma,
                           const float* __restrict__ beta, float n_inv) {
    int t = threadIdx.x;
    float mean = g_stats[512 + t] * n_inv;
    float var  = g_stats[768 + t] * n_inv - mean * mean;
    float sc   = gamma[t] * rsqrtf(var + BN_EPS);
    g_scale2[t] = sc;
    g_shift2[t] = beta[t] - mean * sc;
}

// Fold BN1 into W1: W1p[k][j] = scale1[k] * W1[k][j]
__global__ void k_w1_scale(const float* __restrict__ W1) {
    int idx = blockIdx.x * blockDim.x + threadIdx.x;  // K*H = 65536
    g_W1p[idx] = W1[idx] * g_scale1[idx >> 8];
}

// b1p[j] = b1[j] + sum_k shift1[k] * W1[k][j]   (one block per j)
__global__ void k_b1_prep(const float* __restrict__ W1,
                          const float* __restrict__ b1) {
    __shared__ float red[256];
    int j = blockIdx.x;
    int t = threadIdx.x;
    red[t] = g_shift1[t] * W1[t * N_H + j];
    __syncthreads();
    for (int s = 128; s > 0; s >>= 1) {
        if (t < s) red[t] += red[t + s];
        __syncthreads();
    }
    if (t == 0) g_b1p[j] = b1[j] + red[0];
}

// ---------------------------------------------------------------------------
// GEMM 1: g_h[M,256] = x_cat[M,256] @ g_W1p[256,256] + g_b1p
//   x_cat(row,k) = k<128 ? input[row][k] : g_agg[row][k-128]
// Tiles: BM=BN=128, BK=8, 256 threads, 8x8 per thread.
// ---------------------------------------------------------------------------
#define GBM 128
#define GBN 128
#define GBK 8

__global__ __launch_bounds__(256)
void k_gemm1(const float* __restrict__ input, int M) {
    __shared__ float As[GBK][GBM];
    __shared__ float Bs[GBK][GBN];
    const int tid = threadIdx.x;
    const int block_row = blockIdx.y * GBM;
    const int block_col = blockIdx.x * GBN;
    const int tx = tid & 15, ty = tid >> 4;
    const int aRow = tid >> 1;
    const int aCol = (tid & 1) * 4;
    const int bRow = tid >> 5;
    const int bCol = (tid & 31) * 4;

    float acc[8][8];
#pragma unroll
    for (int i = 0; i < 8; i++)
#pragma unroll
        for (int j = 0; j < 8; j++) acc[i][j] = 0.f;

    for (int k0 = 0; k0 < N_CAT; k0 += GBK) {
        int gRow = block_row + aRow;
        float4 av = make_float4(0.f, 0.f, 0.f, 0.f);
        if (gRow < M) {
            int k = k0 + aCol;   // k%4==0, never straddles 128
            const float* src = (k < N_D) ? (input + (size_t)gRow * N_D + k)
                                         : (g_agg + (size_t)gRow * N_D + (k - N_D));
            av = *reinterpret_cast<const float4*>(src);
        }
        As[aCol + 0][aRow] = av.x;
        As[aCol + 1][aRow] = av.y;
        As[aCol + 2][aRow] = av.z;
        As[aCol + 3][aRow] = av.w;

        *reinterpret_cast<float4*>(&Bs[bRow][bCol]) =
            *reinterpret_cast<const float4*>(&g_W1p[(size_t)(k0 + bRow) * N_H + block_col + bCol]);
        __syncthreads();

#pragma unroll
        for (int k = 0; k < GBK; k++) {
            float ar[8], br[8];
#pragma unroll
            for (int i = 0; i < 8; i++) ar[i] = As[k][ty * 8 + i];
#pragma unroll
            for (int j = 0; j < 8; j++) br[j] = Bs[k][tx * 8 + j];
#pragma unroll
            for (int i = 0; i < 8; i++)
#pragma unroll
                for (int j = 0; j < 8; j++) acc[i][j] += ar[i] * br[j];
        }
        __syncthreads();
    }

#pragma unroll
    for (int i = 0; i < 8; i++) {
        int r = block_row + ty * 8 + i;
        if (r >= M) continue;
#pragma unroll
        for (int j = 0; j < 8; j += 4) {
            int c = block_col + tx * 8 + j;
            float4 o;
            o.x = acc[i][j + 0] + g_b1p[c + 0];
            o.y = acc[i][j + 1] + g_b1p[c + 1];
            o.z = acc[i][j + 2] + g_b1p[c + 2];
            o.w = acc[i][j + 3] + g_b1p[c + 3];
            *reinterpret_cast<float4*>(&g_h[(size_t)r * N_H + c]) = o;
        }
    }
}

// ---------------------------------------------------------------------------
// GEMM 2: out[M,128] = relu(g_h * scale2 + shift2) @ W2[256,128] + b2
// ---------------------------------------------------------------------------
__global__ __launch_bounds__(256)
void k_gemm2(const float* __restrict__ W2, const float* __restrict__ b2,
             float* __restrict__ out, int M) {
    __shared__ float As[GBK][GBM];
    __shared__ float Bs[GBK][GBN];
    const int tid = threadIdx.x;
    const int block_row = blockIdx.y * GBM;
    const int tx = tid & 15, ty = tid >> 4;
    const int aRow = tid >> 1;
    const int aCol = (tid & 1) * 4;
    const int bRow = tid >> 5;
    const int bCol = (tid & 31) * 4;

    float acc[8][8];
#pragma unroll
    for (int i = 0; i < 8; i++)
#pragma unroll
        for (int j = 0; j < 8; j++) acc[i][j] = 0.f;

    for (int k0 = 0; k0 < N_H; k0 += GBK) {
        int gRow = block_row + aRow;
        float4 av = make_float4(0.f, 0.f, 0.f, 0.f);
        if (gRow < M) {
            int k = k0 + aCol;
            av = *reinterpret_cast<const float4*>(&g_h[(size_t)gRow * N_H + k]);
            av.x = fmaxf(av.x * g_scale2[k + 0] + g_shift2[k + 0], 0.f);
            av.y = fmaxf(av.y * g_scale2[k + 1] + g_shift2[k + 1], 0.f);
            av.z = fmaxf(av.z * g_scale2[k + 2] + g_shift2[k + 2], 0.f);
            av.w = fmaxf(av.w * g_scale2[k + 3] + g_shift2[k + 3], 0.f);
        }
        As[aCol + 0][aRow] = av.x;
        As[aCol + 1][aRow] = av.y;
        As[aCol + 2][aRow] = av.z;
        As[aCol + 3][aRow] = av.w;

        // N = 128: only bCol < 128 lanes load real data (bCol in [0,124])
        *reinterpret_cast<float4*>(&Bs[bRow][bCol]) =
            *reinterpret_cast<const float4*>(&W2[(size_t)(k0 + bRow) * N_D + bCol]);
        __syncthreads();

#pragma unroll
        for (int k = 0; k < GBK; k++) {
            float ar[8], br[8];
#pragma unroll
            for (int i = 0; i < 8; i++) ar[i] = As[k][ty * 8 + i];
#pragma unroll
            for (int j = 0; j < 8; j++) br[j] = Bs[k][tx * 8 + j];
#pragma unroll
            for (int i = 0; i < 8; i++)
#pragma unroll
                for (int j = 0; j < 8; j++) acc[i][j] += ar[i] * br[j];
        }
        __syncthreads();
    }

#pragma unroll
    for (int i = 0; i < 8; i++) {
        int r = block_row + ty * 8 + i;
        if (r >= M) continue;
#pragma unroll
        for (int j = 0; j < 8; j += 4) {
            int c = tx * 8 + j;   // block_col == 0 (N=128 fits one tile)
            float4 o;
            o.x = acc[i][j + 0] + b2[c + 0];
            o.y = acc[i][j + 1] + b2[c + 1];
            o.z = acc[i][j + 2] + b2[c + 2];
            o.w = acc[i][j + 3] + b2[c + 3];
            *reinterpret_cast<float4*>(&out[(size_t)r * N_D + c]) = o;
        }
    }
}

// ---------------------------------------------------------------------------
// Launch
// ---------------------------------------------------------------------------
extern "C" void kernel_launch(void* const* d_in, const int* in_sizes, int n_in,
                              void* d_out, int out_size) {
    const float* input  = (const float*)d_in[0];
    const int*   rows   = (const int*)  d_in[1];
    const int*   cols   = (const int*)  d_in[2];
    const float* vals   = (const float*)d_in[3];
    const float* gamma1 = (const float*)d_in[4];
    const float* beta1  = (const float*)d_in[5];
    const float* W1     = (const float*)d_in[6];
    const float* b1     = (const float*)d_in[7];
    const float* gamma2 = (const float*)d_in[8];
    const float* beta2  = (const float*)d_in[9];
    const float* W2     = (const float*)d_in[10];
    const float* b2     = (const float*)d_in[11];
    float* out = (float*)d_out;

    const int n = in_sizes[0] / N_D;   // 100000
    const int E = in_sizes[1];         // 1600000
    const float n_inv = 1.0f / (float)n;

    // 1. zero scratch (agg + all 1024 stats slots)
    {
        size_t n4 = (size_t)n * N_D / 4;
        int blocks = (int)((n4 + 255) / 256);
        k_zero<<<blocks, 256>>>(n4);
    }
    // 2. SpMM scatter-add
    {
        int warps = E;
        int blocks = (warps * 32 + 255) / 256;
        k_spmm<<<blocks, 256>>>(input, rows, cols, vals, E);
    }
    // 3. stats of x_cat
    k_stats_cat<<<512, 256>>>(input, n);
    // 4. BN1 params
    k_bn1_prep<<<1, 256>>>(gamma1, beta1, n_inv);
    // 5. fold BN1 into W1/b1
    k_w1_scale<<<(N_CAT * N_H) / 256, 256>>>(W1);
    k_b1_prep<<<N_H, 256>>>(W1, b1);
    // 6. GEMM1 -> g_h
    {
        dim3 grid(N_H / GBN, (n + GBM - 1) / GBM);
        k_gemm1<<<grid, 256>>>(input, n);
    }
    // 7. stats of h
    k_stats_h<<<512, 256>>>(n);
    // 8. BN2 params
    k_bn2_prep<<<1, 256>>>(gamma2, beta2, n_inv);
    // 9. GEMM2 (BN2+ReLU fused into A load) -> out
    {
        dim3 grid(1, (n + GBM - 1) / GBM);
        k_gemm2<<<grid, 256>>>(W2, b2, out, n);
    }
}

// round 4
// speedup vs baseline: 1.5314x; 1.5314x over previous
#include <cuda_runtime.h>
#include <cstdint>
#include <cstddef>

#define N_D   128
#define N_H   256
#define N_CAT 256
#define BN_EPS 1e-5f
#define MAXN  100000

// ---------------------------------------------------------------------------
// Scratch
// ---------------------------------------------------------------------------
__device__ __align__(1024) float g_agg[(size_t)MAXN * N_D];   // 51.2 MB
__device__ __align__(1024) float g_h  [(size_t)MAXN * N_H];   // 102.4 MB
__device__ float g_stats[4 * 256];
__device__ float g_scale1[N_CAT], g_shift1[N_CAT];
__device__ float g_scale2[N_H],  g_shift2[N_H];
__device__ __align__(16) uint32_t g_W1t[N_H * N_CAT];  // [n][k] BN1-folded, tf32 bits
__device__ __align__(16) uint32_t g_W2t[N_D * N_H];    // [n][k] tf32 bits
__device__ float g_b1p[N_H];

// ---------------------------------------------------------------------------
// Helpers
// ---------------------------------------------------------------------------
__device__ __forceinline__ uint32_t f2tf32(float x) {
    uint32_t r;
    asm("cvt.rna.tf32.f32 %0, %1;" : "=r"(r) : "f"(x));
    return r;
}
__device__ __forceinline__ void mma_tf32(float d[4], const uint32_t a[4],
                                         const uint32_t b[2]) {
    asm volatile(
        "mma.sync.aligned.m16n8k8.row.col.f32.tf32.tf32.f32 "
        "{%0,%1,%2,%3}, {%4,%5,%6,%7}, {%8,%9}, {%0,%1,%2,%3};"
        : "+f"(d[0]), "+f"(d[1]), "+f"(d[2]), "+f"(d[3])
        : "r"(a[0]), "r"(a[1]), "r"(a[2]), "r"(a[3]), "r"(b[0]), "r"(b[1]));
}

// ---------------------------------------------------------------------------
// Small kernels
// ---------------------------------------------------------------------------
__global__ void k_zero(size_t n4) {
    size_t i = (size_t)blockIdx.x * blockDim.x + threadIdx.x;
    size_t stride = (size_t)gridDim.x * blockDim.x;
    float4* p = reinterpret_cast<float4*>(g_agg);
    float4 z = make_float4(0.f, 0.f, 0.f, 0.f);
    for (; i < n4; i += stride) p[i] = z;
    if (blockIdx.x == 0)
        for (int j = threadIdx.x; j < 4 * 256; j += blockDim.x) g_stats[j] = 0.f;
}

__global__ void k_spmm(const float* __restrict__ x, const int* __restrict__ rows,
                       const int* __restrict__ cols, const float* __restrict__ vals, int E) {
    int widx = (int)(((size_t)blockIdx.x * blockDim.x + threadIdx.x) >> 5);
    int lane = threadIdx.x & 31;
    if (widx >= E) return;
    int r = rows[widx], c = cols[widx];
    float v = vals[widx];
    float4 m = reinterpret_cast<const float4*>(x + (size_t)c * N_D)[lane];
    float* dst = g_agg + (size_t)r * N_D + lane * 4;
    asm volatile("red.global.add.v4.f32 [%0], {%1,%2,%3,%4};"
                 :: "l"(dst), "f"(v * m.x), "f"(v * m.y), "f"(v * m.z), "f"(v * m.w)
                 : "memory");
}

__global__ void k_stats_cat(const float* __restrict__ x, int n) {
    int t = threadIdx.x;
    const float* base = (t < N_D) ? (x + t) : (g_agg + (t - N_D));
    float s = 0.f, sq = 0.f;
    for (int r = blockIdx.x; r < n; r += gridDim.x) {
        float v = base[(size_t)r * N_D];
        s += v; sq += v * v;
    }
    atomicAdd(&g_stats[t], s);
    atomicAdd(&g_stats[256 + t], sq);
}

__global__ void k_stats_h(int n) {
    int t = threadIdx.x;
    float s = 0.f, sq = 0.f;
    for (int r = blockIdx.x; r < n; r += gridDim.x) {
        float v = g_h[(size_t)r * N_H + t];
        s += v; sq += v * v;
    }
    atomicAdd(&g_stats[512 + t], s);
    atomicAdd(&g_stats[768 + t], sq);
}

__global__ void k_bn1_prep(const float* __restrict__ gamma, const float* __restrict__ beta,
                           float n_inv) {
    int t = threadIdx.x;
    float mean = g_stats[t] * n_inv;
    float var  = g_stats[256 + t] * n_inv - mean * mean;
    float sc   = gamma[t] * rsqrtf(var + BN_EPS);
    g_scale1[t] = sc;
    g_shift1[t] = beta[t] - mean * sc;
}

__global__ void k_bn2_prep(const float* __restrict__ gamma, const float* __restrict__ beta,
                           float n_inv) {
    int t = threadIdx.x;
    float mean = g_stats[512 + t] * n_inv;
    float var  = g_stats[768 + t] * n_inv - mean * mean;
    float sc   = gamma[t] * rsqrtf(var + BN_EPS);
    g_scale2[t] = sc;
    g_shift2[t] = beta[t] - mean * sc;
}

// Block j: W1t[j][k] (folded+rounded), b1p[j]; for j<128 also W2t[j][k]
__global__ void k_wprep(const float* __restrict__ W1, const float* __restrict__ b1,
                        const float* __restrict__ W2) {
    __shared__ float red[256];
    int j = blockIdx.x, t = threadIdx.x;
    float w = W1[(size_t)t * N_H + j];
    g_W1t[(size_t)j * N_CAT + t] = f2tf32(g_scale1[t] * w);
    red[t] = g_shift1[t] * w;
    if (j < N_D)
        g_W2t[(size_t)j * N_H + t] = f2tf32(W2[(size_t)t * N_D + j]);
    __syncthreads();
    for (int s = 128; s > 0; s >>= 1) {
        if (t < s) red[t] += red[t + s];
        __syncthreads();
    }
    if (t == 0) g_b1p[j] = b1[j] + red[0];
}

// ---------------------------------------------------------------------------
// GEMM via mma.sync m16n8k8 tf32.
// CTA tile 128x128, 8 warps (4M x 2N), warp tile 32x64. K in chunks of 32.
// ---------------------------------------------------------------------------
#define PAD 36   // word stride: 16B-aligned uint4 stores, conflict-free frag reads

// GEMM1: g_h[M,256] = [input|g_agg] @ W1t^T + b1p
__global__ __launch_bounds__(256, 2)
void k_gemm1_mma(const float* __restrict__ input, int M) {
    __shared__ uint32_t As[128][PAD];
    __shared__ uint32_t Bs[128][PAD];
    const int tid = threadIdx.x, wid = tid >> 5, lane = tid & 31;
    const int warp_m = wid & 3, warp_n = wid >> 2;
    const int grp = lane >> 2, tig = lane & 3;
    const int block_row = blockIdx.y * 128;
    const int block_col = blockIdx.x * 128;

    float d[2][8][4];
#pragma unroll
    for (int mt = 0; mt < 2; mt++)
#pragma unroll
        for (int nt = 0; nt < 8; nt++)
#pragma unroll
            for (int q = 0; q < 4; q++) d[mt][nt][q] = 0.f;

    for (int c = 0; c < 8; c++) {
        const float* asrc = (c < 4) ? input : g_agg;
        const int kofs = (c & 3) * 32;
        __syncthreads();
        // A: 128 rows x 32 k (tf32-convert); 4 float4 per thread
#pragma unroll
        for (int i = 0; i < 4; i++) {
            int f = i * 256 + tid, row = f >> 3, c4 = f & 7;
            int grow = block_row + row;
            float4 v = make_float4(0.f, 0.f, 0.f, 0.f);
            if (grow < M)
                v = *reinterpret_cast<const float4*>(asrc + (size_t)grow * N_D + kofs + c4 * 4);
            *reinterpret_cast<uint4*>(&As[row][c4 * 4]) =
                make_uint4(f2tf32(v.x), f2tf32(v.y), f2tf32(v.z), f2tf32(v.w));
        }
        // B: 128 n-rows x 32 k (pre-rounded)
#pragma unroll
        for (int i = 0; i < 4; i++) {
            int f = i * 256 + tid, row = f >> 3, c4 = f & 7;
            uint4 v = *reinterpret_cast<const uint4*>(
                &g_W1t[(size_t)(block_col + row) * N_CAT + c * 32 + c4 * 4]);
            *reinterpret_cast<uint4*>(&Bs[row][c4 * 4]) = v;
        }
        __syncthreads();

#pragma unroll
        for (int ks = 0; ks < 4; ks++) {
            uint32_t a[2][4], b[8][2];
            const int kc = ks * 8 + tig;
#pragma unroll
            for (int mt = 0; mt < 2; mt++) {
                int rb = warp_m * 32 + mt * 16 + grp;
                a[mt][0] = As[rb][kc];
                a[mt][1] = As[rb + 8][kc];
                a[mt][2] = As[rb][kc + 4];
                a[mt][3] = As[rb + 8][kc + 4];
            }
#pragma unroll
            for (int nt = 0; nt < 8; nt++) {
                int nb = warp_n * 64 + nt * 8 + grp;
                b[nt][0] = Bs[nb][kc];
                b[nt][1] = Bs[nb][kc + 4];
            }
#pragma unroll
            for (int mt = 0; mt < 2; mt++)
#pragma unroll
                for (int nt = 0; nt < 8; nt++) mma_tf32(d[mt][nt], a[mt], b[nt]);
        }
    }

    // epilogue: +b1p, write g_h
#pragma unroll
    for (int mt = 0; mt < 2; mt++) {
        int r0 = block_row + warp_m * 32 + mt * 16 + grp;
#pragma unroll
        for (int nt = 0; nt < 8; nt++) {
            int col = block_col + warp_n * 64 + nt * 8 + tig * 2;
            float bx = g_b1p[col], by = g_b1p[col + 1];
            if (r0 < M)
                *reinterpret_cast<float2*>(&g_h[(size_t)r0 * N_H + col]) =
                    make_float2(d[mt][nt][0] + bx, d[mt][nt][1] + by);
            if (r0 + 8 < M)
                *reinterpret_cast<float2*>(&g_h[(size_t)(r0 + 8) * N_H + col]) =
                    make_float2(d[mt][nt][2] + bx, d[mt][nt][3] + by);
        }
    }
}

// GEMM2: out[M,128] = relu(g_h*scale2+shift2) @ W2t^T + b2
__global__ __launch_bounds__(256, 2)
void k_gemm2_mma(const float* __restrict__ b2, float* __restrict__ out, int M) {
    __shared__ uint32_t As[128][PAD];
    __shared__ uint32_t Bs[128][PAD];
    const int tid = threadIdx.x, wid = tid >> 5, lane = tid & 31;
    const int warp_m = wid & 3, warp_n = wid >> 2;
    const int grp = lane >> 2, tig = lane & 3;
    const int block_row = blockIdx.y * 128;

    float d[2][8][4];
#pragma unroll
    for (int mt = 0; mt < 2; mt++)
#pragma unroll
        for (int nt = 0; nt < 8; nt++)
#pragma unroll
            for (int q = 0; q < 4; q++) d[mt][nt][q] = 0.f;

    for (int c = 0; c < 8; c++) {
        __syncthreads();
        // A: relu(h*scale2+shift2), tf32
#pragma unroll
        for (int i = 0; i < 4; i++) {
            int f = i * 256 + tid, row = f >> 3, c4 = f & 7;
            int grow = block_row + row;
            int k = c * 32 + c4 * 4;
            float4 v = make_float4(0.f, 0.f, 0.f, 0.f);
            if (grow < M) {
                v = *reinterpret_cast<const float4*>(&g_h[(size_t)grow * N_H + k]);
                float4 sc = *reinterpret_cast<const float4*>(&g_scale2[k]);
                float4 sh = *reinterpret_cast<const float4*>(&g_shift2[k]);
                v.x = fmaxf(v.x * sc.x + sh.x, 0.f);
                v.y = fmaxf(v.y * sc.y + sh.y, 0.f);
                v.z = fmaxf(v.z * sc.z + sh.z, 0.f);
                v.w = fmaxf(v.w * sc.w + sh.w, 0.f);
            }
            *reinterpret_cast<uint4*>(&As[row][c4 * 4]) =
                make_uint4(f2tf32(v.x), f2tf32(v.y), f2tf32(v.z), f2tf32(v.w));
        }
        // B: 128 n-rows x 32 k
#pragma unroll
        for (int i = 0; i < 4; i++) {
            int f = i * 256 + tid, row = f >> 3, c4 = f & 7;
            uint4 v = *reinterpret_cast<const uint4*>(
                &g_W2t[(size_t)row * N_H + c * 32 + c4 * 4]);
            *reinterpret_cast<uint4*>(&Bs[row][c4 * 4]) = v;
        }
        __syncthreads();

#pragma unroll
        for (int ks = 0; ks < 4; ks++) {
            uint32_t a[2][4], b[8][2];
            const int kc = ks * 8 + tig;
#pragma unroll
            for (int mt = 0; mt < 2; mt++) {
                int rb = warp_m * 32 + mt * 16 + grp;
                a[mt][0] = As[rb][kc];
                a[mt][1] = As[rb + 8][kc];
                a[mt][2] = As[rb][kc + 4];
                a[mt][3] = As[rb + 8][kc + 4];
            }
#pragma unroll
            for (int nt = 0; nt < 8; nt++) {
                int nb = warp_n * 64 + nt * 8 + grp;
                b[nt][0] = Bs[nb][kc];
                b[nt][1] = Bs[nb][kc + 4];
            }
#pragma unroll
            for (int mt = 0; mt < 2; mt++)
#pragma unroll
                for (int nt = 0; nt < 8; nt++) mma_tf32(d[mt][nt], a[mt], b[nt]);
        }
    }

#pragma unroll
    for (int mt = 0; mt < 2; mt++) {
        int r0 = block_row + warp_m * 32 + mt * 16 + grp;
#pragma unroll
        for (int nt = 0; nt < 8; nt++) {
            int col = warp_n * 64 + nt * 8 + tig * 2;
            float bx = b2[col], by = b2[col + 1];
            if (r0 < M)
                *reinterpret_cast<float2*>(&out[(size_t)r0 * N_D + col]) =
                    make_float2(d[mt][nt][0] + bx, d[mt][nt][1] + by);
            if (r0 + 8 < M)
                *reinterpret_cast<float2*>(&out[(size_t)(r0 + 8) * N_D + col]) =
                    make_float2(d[mt][nt][2] + bx, d[mt][nt][3] + by);
        }
    }
}

// ---------------------------------------------------------------------------
// Launch
// ---------------------------------------------------------------------------
extern "C" void kernel_launch(void* const* d_in, const int* in_sizes, int n_in,
                              void* d_out, int out_size) {
    const float* input  = (const float*)d_in[0];
    const int*   rows   = (const int*)  d_in[1];
    const int*   cols   = (const int*)  d_in[2];
    const float* vals   = (const float*)d_in[3];
    const float* gamma1 = (const float*)d_in[4];
    const float* beta1  = (const float*)d_in[5];
    const float* W1     = (const float*)d_in[6];
    const float* b1     = (const float*)d_in[7];
    const float* gamma2 = (const float*)d_in[8];
    const float* beta2  = (const float*)d_in[9];
    const float* W2     = (const float*)d_in[10];
    const float* b2     = (const float*)d_in[11];
    float* out = (float*)d_out;

    const int n = in_sizes[0] / N_D;
    const int E = in_sizes[1];
    const float n_inv = 1.0f / (float)n;

    // 0
    {
        size_t n4 = (size_t)n * N_D / 4;
        k_zero<<<(int)((n4 + 255) / 256), 256>>>(n4);
    }
    // 1
    k_spmm<<<(E * 32 + 255) / 256, 256>>>(input, rows, cols, vals, E);
    // 2
    k_stats_cat<<<512, 256>>>(input, n);
    // 3
    k_bn1_prep<<<1, 256>>>(gamma1, beta1, n_inv);
    // 4
    k_wprep<<<256, 256>>>(W1, b1, W2);
    // 5  <- ncu -s 5 lands here (GEMM1)
    {
        dim3 grid(2, (n + 127) / 128);
        k_gemm1_mma<<<grid, 256>>>(input, n);
    }
    // 6
    k_stats_h<<<512, 256>>>(n);
    // 7
    k_bn2_prep<<<1, 256>>>(gamma2, beta2, n_inv);
    // 8
    {
        dim3 grid(1, (n + 127) / 128);
        k_gemm2_mma<<<grid, 256>>>(b2, out, n);
    }
}

// round 5
// speedup vs baseline: 1.7922x; 1.1703x over previous
#include <cuda_runtime.h>
#include <cstdint>
#include <cstddef>

#define N_D   128
#define N_H   256
#define N_CAT 256
#define BN_EPS 1e-5f
#define MAXN  100000

// ---------------------------------------------------------------------------
// Scratch
// ---------------------------------------------------------------------------
__device__ __align__(1024) float g_agg[(size_t)MAXN * N_D];   // 51.2 MB
__device__ __align__(1024) float g_h  [(size_t)MAXN * N_H];   // 102.4 MB
__device__ float g_stats[4 * 256];
__device__ float g_scale1[N_CAT], g_shift1[N_CAT];
__device__ float g_scale2[N_H],  g_shift2[N_H];
__device__ __align__(16) uint32_t g_W1t[N_H * N_CAT];  // [n][k] BN1-folded, tf32 bits
__device__ __align__(16) uint32_t g_W2t[N_D * N_H];    // [n][k] tf32 bits
__device__ float g_b1p[N_H];

// ---------------------------------------------------------------------------
// Helpers
// ---------------------------------------------------------------------------
__device__ __forceinline__ uint32_t f2tf32(float x) {
    uint32_t r;
    asm("cvt.rna.tf32.f32 %0, %1;" : "=r"(r) : "f"(x));
    return r;
}
__device__ __forceinline__ uint32_t smem_u32(const void* p) {
    uint32_t a;
    asm("{ .reg .u64 t; cvta.to.shared.u64 t, %1; cvt.u32.u64 %0, t; }" : "=r"(a) : "l"(p));
    return a;
}
__device__ __forceinline__ void cp16(uint32_t dst, const void* src, bool pred) {
    int sz = pred ? 16 : 0;
    asm volatile("cp.async.cg.shared.global [%0], [%1], 16, %2;"
                 :: "r"(dst), "l"(src), "r"(sz) : "memory");
}
#define CP_COMMIT() asm volatile("cp.async.commit_group;" ::: "memory")
#define CP_WAIT1()  asm volatile("cp.async.wait_group 1;" ::: "memory")
__device__ __forceinline__ void mma_tf32(float d[4], const uint32_t a[4],
                                         const uint32_t b[2]) {
    asm volatile(
        "mma.sync.aligned.m16n8k8.row.col.f32.tf32.tf32.f32 "
        "{%0,%1,%2,%3}, {%4,%5,%6,%7}, {%8,%9}, {%0,%1,%2,%3};"
        : "+f"(d[0]), "+f"(d[1]), "+f"(d[2]), "+f"(d[3])
        : "r"(a[0]), "r"(a[1]), "r"(a[2]), "r"(a[3]), "r"(b[0]), "r"(b[1]));
}

// ---------------------------------------------------------------------------
// Small kernels
// ---------------------------------------------------------------------------
__global__ void k_zero(size_t n4) {
    size_t i = (size_t)blockIdx.x * blockDim.x + threadIdx.x;
    size_t stride = (size_t)gridDim.x * blockDim.x;
    float4* p = reinterpret_cast<float4*>(g_agg);
    float4 z = make_float4(0.f, 0.f, 0.f, 0.f);
    for (; i < n4; i += stride) p[i] = z;
    if (blockIdx.x == 0)
        for (int j = threadIdx.x; j < 4 * 256; j += blockDim.x) g_stats[j] = 0.f;
}

__global__ void k_spmm(const float* __restrict__ x, const int* __restrict__ rows,
                       const int* __restrict__ cols, const float* __restrict__ vals, int E) {
    int widx = (int)(((size_t)blockIdx.x * blockDim.x + threadIdx.x) >> 5);
    int lane = threadIdx.x & 31;
    if (widx >= E) return;
    int r = rows[widx], c = cols[widx];
    float v = vals[widx];
    float4 m = reinterpret_cast<const float4*>(x + (size_t)c * N_D)[lane];
    float* dst = g_agg + (size_t)r * N_D + lane * 4;
    asm volatile("red.global.add.v4.f32 [%0], {%1,%2,%3,%4};"
                 :: "l"(dst), "f"(v * m.x), "f"(v * m.y), "f"(v * m.z), "f"(v * m.w)
                 : "memory");
}

// stats of input half (cols 0..127)
__global__ void k_stats_input(const float* __restrict__ x, int n) {
    int t = threadIdx.x;   // 0..127
    float s = 0.f, sq = 0.f;
    for (int r = blockIdx.x; r < n; r += gridDim.x) {
        float v = x[(size_t)r * N_D + t];
        s += v; sq += v * v;
    }
    atomicAdd(&g_stats[t], s);
    atomicAdd(&g_stats[256 + t], sq);
}

// stats of agg half (cols 128..255)
__global__ void k_stats_agg(int n) {
    int t = threadIdx.x;   // 0..127
    float s = 0.f, sq = 0.f;
    for (int r = blockIdx.x; r < n; r += gridDim.x) {
        float v = g_agg[(size_t)r * N_D + t];
        s += v; sq += v * v;
    }
    atomicAdd(&g_stats[128 + t], s);
    atomicAdd(&g_stats[384 + t], sq);
}

__global__ void k_stats_h(int n) {
    int t = threadIdx.x;
    float s = 0.f, sq = 0.f;
    for (int r = blockIdx.x; r < n; r += gridDim.x) {
        float v = g_h[(size_t)r * N_H + t];
        s += v; sq += v * v;
    }
    atomicAdd(&g_stats[512 + t], s);
    atomicAdd(&g_stats[768 + t], sq);
}

__global__ void k_bn1_prep(const float* __restrict__ gamma, const float* __restrict__ beta,
                           float n_inv) {
    int t = threadIdx.x;
    float mean = g_stats[t] * n_inv;
    float var  = g_stats[256 + t] * n_inv - mean * mean;
    float sc   = gamma[t] * rsqrtf(var + BN_EPS);
    g_scale1[t] = sc;
    g_shift1[t] = beta[t] - mean * sc;
}

__global__ void k_bn2_prep(const float* __restrict__ gamma, const float* __restrict__ beta,
                           float n_inv) {
    int t = threadIdx.x;
    float mean = g_stats[512 + t] * n_inv;
    float var  = g_stats[768 + t] * n_inv - mean * mean;
    float sc   = gamma[t] * rsqrtf(var + BN_EPS);
    g_scale2[t] = sc;
    g_shift2[t] = beta[t] - mean * sc;
}

__global__ void k_w2prep(const float* __restrict__ W2) {
    int j = blockIdx.x, t = threadIdx.x;   // j<128, t<256
    g_W2t[(size_t)j * N_H + t] = f2tf32(W2[(size_t)t * N_D + j]);
}

__global__ void k_w1prep(const float* __restrict__ W1, const float* __restrict__ b1) {
    __shared__ float red[256];
    int j = blockIdx.x, t = threadIdx.x;
    float w = W1[(size_t)t * N_H + j];
    g_W1t[(size_t)j * N_CAT + t] = f2tf32(g_scale1[t] * w);
    red[t] = g_shift1[t] * w;
    __syncthreads();
    for (int s = 128; s > 0; s >>= 1) {
        if (t < s) red[t] += red[t + s];
        __syncthreads();
    }
    if (t == 0) g_b1p[j] = b1[j] + red[0];
}

// ---------------------------------------------------------------------------
// GEMMs: mma.sync m16n8k8 tf32, CTA tile 128x128, 8 warps (4Mx2N),
// cp.async 2-stage pipeline. Dynamic smem: 2 stages x (A,B) x 128 x PADW words.
// ---------------------------------------------------------------------------
#define PADW 36
#define MAT_WORDS (128 * PADW)                 // 4608 words = 18KB
#define STAGE_WORDS (2 * MAT_WORDS)            // A+B
#define PIPE_BYTES (2 * STAGE_WORDS * 4)       // 73728
#define G2_SMEM (PIPE_BYTES + 512 * 4)         // + scale2/shift2 cache

// GEMM1: g_h[M,256] = [input|g_agg] @ W1t^T + b1p
__global__ __launch_bounds__(256, 2)
void k_gemm1_mma(const float* __restrict__ input, int M) {
    extern __shared__ uint32_t sm[];
    const uint32_t sbase = smem_u32(sm);
    const int tid = threadIdx.x, wid = tid >> 5, lane = tid & 31;
    const int warp_m = wid & 3, warp_n = wid >> 2;
    const int grp = lane >> 2, tig = lane & 3;
    const int block_row = blockIdx.y * 128;
    const int block_col = blockIdx.x * 128;

    const int lrow = tid >> 1;            // 0..127
    const int lc4  = (tid & 1) * 4;       // 0 or 4 (x2 float4 per row handled below)

    float d[2][8][4];
#pragma unroll
    for (int mt = 0; mt < 2; mt++)
#pragma unroll
        for (int nt = 0; nt < 8; nt++)
#pragma unroll
            for (int q = 0; q < 4; q++) d[mt][nt][q] = 0.f;

    // issue chunk c into stage s
    auto issue = [&](int c, int s) {
        const float* asrc = (c < 4) ? input : g_agg;
        const int kofs = (c & 3) * 32;
        uint32_t abase = sbase + (s * STAGE_WORDS) * 4;
        uint32_t bbase = abase + MAT_WORDS * 4;
#pragma unroll
        for (int i = 0; i < 2; i++) {
            int c4 = lc4 + i * (tid & 1 ? -4 : 0);   // not used; simple form below
        }
        // 4 cp16 per thread per matrix half: f = i*256+tid
#pragma unroll
        for (int i = 0; i < 4; i++) {
            int f = i * 256 + tid, row = f >> 3, c4 = f & 7;
            bool p = (block_row + row) < M;
            cp16(abase + (row * PADW + c4 * 4) * 4,
                 asrc + (size_t)(block_row + row) * N_D + kofs + c4 * 4, p);
            cp16(bbase + (row * PADW + c4 * 4) * 4,
                 &g_W1t[(size_t)(block_col + row) * N_CAT + c * 32 + c4 * 4], true);
        }
    };

    issue(0, 0); CP_COMMIT();
    issue(1, 1); CP_COMMIT();

    for (int c = 0; c < 8; c++) {
        const int s = c & 1;
        CP_WAIT1();
        __syncthreads();
        const uint32_t* As = sm + s * STAGE_WORDS;
        const uint32_t* Bs = As + MAT_WORDS;
#pragma unroll
        for (int ks = 0; ks < 4; ks++) {
            uint32_t a[2][4], b[8][2];
            const int kc = ks * 8 + tig;
#pragma unroll
            for (int mt = 0; mt < 2; mt++) {
                int rb = warp_m * 32 + mt * 16 + grp;
                a[mt][0] = f2tf32(__uint_as_float(As[rb * PADW + kc]));
                a[mt][1] = f2tf32(__uint_as_float(As[(rb + 8) * PADW + kc]));
                a[mt][2] = f2tf32(__uint_as_float(As[rb * PADW + kc + 4]));
                a[mt][3] = f2tf32(__uint_as_float(As[(rb + 8) * PADW + kc + 4]));
            }
#pragma unroll
            for (int nt = 0; nt < 8; nt++) {
                int nb = warp_n * 64 + nt * 8 + grp;
                b[nt][0] = Bs[nb * PADW + kc];
                b[nt][1] = Bs[nb * PADW + kc + 4];
            }
#pragma unroll
            for (int mt = 0; mt < 2; mt++)
#pragma unroll
                for (int nt = 0; nt < 8; nt++) mma_tf32(d[mt][nt], a[mt], b[nt]);
        }
        __syncthreads();
        if (c + 2 < 8) issue(c + 2, s);
        CP_COMMIT();
    }

    // epilogue: +b1p, write g_h
#pragma unroll
    for (int mt = 0; mt < 2; mt++) {
        int r0 = block_row + warp_m * 32 + mt * 16 + grp;
#pragma unroll
        for (int nt = 0; nt < 8; nt++) {
            int col = block_col + warp_n * 64 + nt * 8 + tig * 2;
            float bx = g_b1p[col], by = g_b1p[col + 1];
            if (r0 < M)
                *reinterpret_cast<float2*>(&g_h[(size_t)r0 * N_H + col]) =
                    make_float2(d[mt][nt][0] + bx, d[mt][nt][1] + by);
            if (r0 + 8 < M)
                *reinterpret_cast<float2*>(&g_h[(size_t)(r0 + 8) * N_H + col]) =
                    make_float2(d[mt][nt][2] + bx, d[mt][nt][3] + by);
        }
    }
}

// GEMM2: out[M,128] = relu(g_h*scale2+shift2) @ W2t^T + b2
__global__ __launch_bounds__(256, 2)
void k_gemm2_mma(const float* __restrict__ b2, float* __restrict__ out, int M) {
    extern __shared__ uint32_t sm[];
    const uint32_t sbase = smem_u32(sm);
    float* scs = reinterpret_cast<float*>(sm + 2 * STAGE_WORDS);
    float* shs = scs + 256;
    const int tid = threadIdx.x, wid = tid >> 5, lane = tid & 31;
    const int warp_m = wid & 3, warp_n = wid >> 2;
    const int grp = lane >> 2, tig = lane & 3;
    const int block_row = blockIdx.y * 128;

    scs[tid] = g_scale2[tid];
    shs[tid] = g_shift2[tid];

    float d[2][8][4];
#pragma unroll
    for (int mt = 0; mt < 2; mt++)
#pragma unroll
        for (int nt = 0; nt < 8; nt++)
#pragma unroll
            for (int q = 0; q < 4; q++) d[mt][nt][q] = 0.f;

    auto issue = [&](int c, int s) {
        uint32_t abase = sbase + (s * STAGE_WORDS) * 4;
        uint32_t bbase = abase + MAT_WORDS * 4;
#pragma unroll
        for (int i = 0; i < 4; i++) {
            int f = i * 256 + tid, row = f >> 3, c4 = f & 7;
            bool p = (block_row + row) < M;
            cp16(abase + (row * PADW + c4 * 4) * 4,
                 &g_h[(size_t)(block_row + row) * N_H + c * 32 + c4 * 4], p);
            cp16(bbase + (row * PADW + c4 * 4) * 4,
                 &g_W2t[(size_t)row * N_H + c * 32 + c4 * 4], true);
        }
    };

    issue(0, 0); CP_COMMIT();
    issue(1, 1); CP_COMMIT();
    __syncthreads();   // also covers scs/shs fill

    for (int c = 0; c < 8; c++) {
        const int s = c & 1;
        CP_WAIT1();
        __syncthreads();
        const uint32_t* As = sm + s * STAGE_WORDS;
        const uint32_t* Bs = As + MAT_WORDS;
#pragma unroll
        for (int ks = 0; ks < 4; ks++) {
            uint32_t a[2][4], b[8][2];
            const int kc = ks * 8 + tig;
            const int k0 = c * 32 + kc, k1 = k0 + 4;
            const float sc0 = scs[k0], sh0 = shs[k0];
            const float sc1 = scs[k1], sh1 = shs[k1];
#pragma unroll
            for (int mt = 0; mt < 2; mt++) {
                int rb = warp_m * 32 + mt * 16 + grp;
                float v0 = __uint_as_float(As[rb * PADW + kc]);
                float v1 = __uint_as_float(As[(rb + 8) * PADW + kc]);
                float v2 = __uint_as_float(As[rb * PADW + kc + 4]);
                float v3 = __uint_as_float(As[(rb + 8) * PADW + kc + 4]);
                a[mt][0] = f2tf32(fmaxf(v0 * sc0 + sh0, 0.f));
                a[mt][1] = f2tf32(fmaxf(v1 * sc0 + sh0, 0.f));
                a[mt][2] = f2tf32(fmaxf(v2 * sc1 + sh1, 0.f));
                a[mt][3] = f2tf32(fmaxf(v3 * sc1 + sh1, 0.f));
            }
#pragma unroll
            for (int nt = 0; nt < 8; nt++) {
                int nb = warp_n * 64 + nt * 8 + grp;
                b[nt][0] = Bs[nb * PADW + kc];
                b[nt][1] = Bs[nb * PADW + kc + 4];
            }
#pragma unroll
            for (int mt = 0; mt < 2; mt++)
#pragma unroll
                for (int nt = 0; nt < 8; nt++) mma_tf32(d[mt][nt], a[mt], b[nt]);
        }
        __syncthreads();
        if (c + 2 < 8) issue(c + 2, s);
        CP_COMMIT();
    }

#pragma unroll
    for (int mt = 0; mt < 2; mt++) {
        int r0 = block_row + warp_m * 32 + mt * 16 + grp;
#pragma unroll
        for (int nt = 0; nt < 8; nt++) {
            int col = warp_n * 64 + nt * 8 + tig * 2;
            float bx = b2[col], by = b2[col + 1];
            if (r0 < M)
                *reinterpret_cast<float2*>(&out[(size_t)r0 * N_D + col]) =
                    make_float2(d[mt][nt][0] + bx, d[mt][nt][1] + by);
            if (r0 + 8 < M)
                *reinterpret_cast<float2*>(&out[(size_t)(r0 + 8) * N_D + col]) =
                    make_float2(d[mt][nt][2] + bx, d[mt][nt][3] + by);
        }
    }
}

// ---------------------------------------------------------------------------
// Launch
// ---------------------------------------------------------------------------
extern "C" void kernel_launch(void* const* d_in, const int* in_sizes, int n_in,
                              void* d_out, int out_size) {
    const float* input  = (const float*)d_in[0];
    const int*   rows   = (const int*)  d_in[1];
    const int*   cols   = (const int*)  d_in[2];
    const float* vals   = (const float*)d_in[3];
    const float* gamma1 = (const float*)d_in[4];
    const float* beta1  = (const float*)d_in[5];
    const float* W1     = (const float*)d_in[6];
    const float* b1     = (const float*)d_in[7];
    const float* gamma2 = (const float*)d_in[8];
    const float* beta2  = (const float*)d_in[9];
    const float* W2     = (const float*)d_in[10];
    const float* b2     = (const float*)d_in[11];
    float* out = (float*)d_out;

    const int n = in_sizes[0] / N_D;
    const int E = in_sizes[1];
    const float n_inv = 1.0f / (float)n;

    cudaFuncSetAttribute(k_gemm1_mma, cudaFuncAttributeMaxDynamicSharedMemorySize, PIPE_BYTES);
    cudaFuncSetAttribute(k_gemm2_mma, cudaFuncAttributeMaxDynamicSharedMemorySize, G2_SMEM);

    // 0: zero agg + stats
    {
        size_t n4 = (size_t)n * N_D / 4;
        k_zero<<<(int)((n4 + 255) / 256), 256>>>(n4);
    }
    // 1: stats of input half (independent of spmm)
    k_stats_input<<<512, 128>>>(input, n);
    // 2: W2 transpose/round (independent)
    k_w2prep<<<128, 256>>>(W2);
    // 3: SpMM  <- ncu profile target
    k_spmm<<<(E * 32 + 255) / 256, 256>>>(input, rows, cols, vals, E);
    // 4: stats of agg half
    k_stats_agg<<<512, 128>>>(n);
    // 5: BN1 params
    k_bn1_prep<<<1, 256>>>(gamma1, beta1, n_inv);
    // 6: fold BN1 into W1 + b1p
    k_w1prep<<<256, 256>>>(W1, b1);
    // 7: GEMM1
    {
        dim3 grid(2, (n + 127) / 128);
        k_gemm1_mma<<<grid, 256, PIPE_BYTES>>>(input, n);
    }
    // 8: stats of h
    k_stats_h<<<512, 256>>>(n);
    // 9: BN2 params
    k_bn2_prep<<<1, 256>>>(gamma2, beta2, n_inv);
    // 10: GEMM2
    {
        dim3 grid(1, (n + 127) / 128);
        k_gemm2_mma<<<grid, 256, G2_SMEM>>>(b2, out, n);
    }
}

// round 6
// speedup vs baseline: 2.4117x; 1.3457x over previous
#include <cuda_runtime.h>
#include <cstdint>
#include <cstddef>

#define N_D   128
#define N_H   256
#define N_CAT 256
#define BN_EPS 1e-5f
#define MAXN  100000

// ---------------------------------------------------------------------------
// Scratch
// ---------------------------------------------------------------------------
__device__ __align__(1024) float g_agg[(size_t)MAXN * N_D];   // 51.2 MB
__device__ __align__(1024) float g_h  [(size_t)MAXN * N_H];   // 102.4 MB
__device__ float g_stats[4 * 256];   // [0:256) sum_cat [256:512) sq_cat [512:768) sum_h [768:1024) sq_h
__device__ __align__(16) uint32_t g_W1t[N_H * N_CAT];  // [n][k] BN1-folded, tf32 bits
__device__ __align__(16) uint32_t g_W2t[N_D * N_H];    // [n][k] tf32 bits
__device__ float g_b1p[N_H];

// ---------------------------------------------------------------------------
// Helpers
// ---------------------------------------------------------------------------
__device__ __forceinline__ uint32_t f2tf32(float x) {
    uint32_t r;
    asm("cvt.rna.tf32.f32 %0, %1;" : "=r"(r) : "f"(x));
    return r;
}
__device__ __forceinline__ uint32_t smem_u32(const void* p) {
    uint32_t a;
    asm("{ .reg .u64 t; cvta.to.shared.u64 t, %1; cvt.u32.u64 %0, t; }" : "=r"(a) : "l"(p));
    return a;
}
__device__ __forceinline__ void cp16(uint32_t dst, const void* src, bool pred) {
    int sz = pred ? 16 : 0;
    asm volatile("cp.async.cg.shared.global [%0], [%1], 16, %2;"
                 :: "r"(dst), "l"(src), "r"(sz) : "memory");
}
#define CP_COMMIT() asm volatile("cp.async.commit_group;" ::: "memory")
#define CP_WAIT1()  asm volatile("cp.async.wait_group 1;" ::: "memory")
__device__ __forceinline__ void mma_tf32(float d[4], const uint32_t a[4],
                                         const uint32_t b[2]) {
    asm volatile(
        "mma.sync.aligned.m16n8k8.row.col.f32.tf32.tf32.f32 "
        "{%0,%1,%2,%3}, {%4,%5,%6,%7}, {%8,%9}, {%0,%1,%2,%3};"
        : "+f"(d[0]), "+f"(d[1]), "+f"(d[2]), "+f"(d[3])
        : "r"(a[0]), "r"(a[1]), "r"(a[2]), "r"(a[3]), "r"(b[0]), "r"(b[1]));
}

// ---------------------------------------------------------------------------
// Small kernels
// ---------------------------------------------------------------------------
__global__ void k_zero(size_t n4) {
    size_t i = (size_t)blockIdx.x * blockDim.x + threadIdx.x;
    size_t stride = (size_t)gridDim.x * blockDim.x;
    float4* p = reinterpret_cast<float4*>(g_agg);
    float4 z = make_float4(0.f, 0.f, 0.f, 0.f);
    for (; i < n4; i += stride) p[i] = z;
    if (blockIdx.x == 0)
        for (int j = threadIdx.x; j < 4 * 256; j += blockDim.x) g_stats[j] = 0.f;
}

// SpMM: 8 edges per warp. Gathers batched before reductions for MLP=8.
__global__ void k_spmm(const float* __restrict__ x, const int* __restrict__ rows,
                       const int* __restrict__ cols, const float* __restrict__ vals, int E) {
    int gw = (int)(((size_t)blockIdx.x * blockDim.x + threadIdx.x) >> 5);
    int lane = threadIdx.x & 31;
    int base = gw * 8;
    if (base >= E) return;

    int e = base + (lane & 7);
    bool ev = e < E;
    int c = ev ? cols[e] : 0;
    int r = ev ? rows[e] : 0;
    float v = ev ? vals[e] : 0.f;

    float4 m[8];
    int ri[8];
    float vi[8];
#pragma unroll
    for (int i = 0; i < 8; i++) {
        int ci = __shfl_sync(0xffffffffu, c, i);
        ri[i]  = __shfl_sync(0xffffffffu, r, i);
        vi[i]  = __shfl_sync(0xffffffffu, v, i);
        m[i] = reinterpret_cast<const float4*>(x + (size_t)ci * N_D)[lane];
    }
#pragma unroll
    for (int i = 0; i < 8; i++) {
        if (base + i < E) {
            float* dst = g_agg + (size_t)ri[i] * N_D + lane * 4;
            asm volatile("red.global.add.v4.f32 [%0], {%1,%2,%3,%4};"
                         :: "l"(dst), "f"(vi[i] * m[i].x), "f"(vi[i] * m[i].y),
                            "f"(vi[i] * m[i].z), "f"(vi[i] * m[i].w) : "memory");
        }
    }
}

__global__ void k_stats_input(const float* __restrict__ x, int n) {
    int t = threadIdx.x;   // 0..127
    float s = 0.f, sq = 0.f;
    for (int r = blockIdx.x; r < n; r += gridDim.x) {
        float v = x[(size_t)r * N_D + t];
        s += v; sq += v * v;
    }
    atomicAdd(&g_stats[t], s);
    atomicAdd(&g_stats[256 + t], sq);
}

__global__ void k_stats_agg(int n) {
    int t = threadIdx.x;   // 0..127
    float s = 0.f, sq = 0.f;
    for (int r = blockIdx.x; r < n; r += gridDim.x) {
        float v = g_agg[(size_t)r * N_D + t];
        s += v; sq += v * v;
    }
    atomicAdd(&g_stats[128 + t], s);
    atomicAdd(&g_stats[384 + t], sq);
}

__global__ void k_w2prep(const float* __restrict__ W2) {
    int j = blockIdx.x, t = threadIdx.x;   // j<128, t<256
    g_W2t[(size_t)j * N_H + t] = f2tf32(W2[(size_t)t * N_D + j]);
}

// BN1 inline + fold into W1, compute b1p. Block j handles output column j.
__global__ void k_w1prep(const float* __restrict__ W1, const float* __restrict__ b1,
                         const float* __restrict__ gamma1, const float* __restrict__ beta1,
                         float n_inv) {
    __shared__ float red[256];
    int j = blockIdx.x, t = threadIdx.x;
    float mean = g_stats[t] * n_inv;
    float var  = g_stats[256 + t] * n_inv - mean * mean;
    float sc   = gamma1[t] * rsqrtf(var + BN_EPS);
    float sh   = beta1[t] - mean * sc;
    float w = W1[(size_t)t * N_H + j];
    g_W1t[(size_t)j * N_CAT + t] = f2tf32(sc * w);
    red[t] = sh * w;
    __syncthreads();
    for (int s = 128; s > 0; s >>= 1) {
        if (t < s) red[t] += red[t + s];
        __syncthreads();
    }
    if (t == 0) g_b1p[j] = b1[j] + red[0];
}

// ---------------------------------------------------------------------------
// GEMMs: mma.sync m16n8k8 tf32, CTA tile 128x128, 8 warps (4Mx2N),
// cp.async 2-stage pipeline.
// ---------------------------------------------------------------------------
#define PADW 36
#define MAT_WORDS (128 * PADW)
#define STAGE_WORDS (2 * MAT_WORDS)
#define PIPE_BYTES (2 * STAGE_WORDS * 4)       // 73728
#define G2_SMEM (PIPE_BYTES + 512 * 4)

// GEMM1: g_h = [input|g_agg] @ W1t^T + b1p ; fused column stats of h -> g_stats[512..]
__global__ __launch_bounds__(256, 2)
void k_gemm1_mma(const float* __restrict__ input, int M) {
    extern __shared__ uint32_t sm[];
    const uint32_t sbase = smem_u32(sm);
    const int tid = threadIdx.x, wid = tid >> 5, lane = tid & 31;
    const int warp_m = wid & 3, warp_n = wid >> 2;
    const int grp = lane >> 2, tig = lane & 3;
    const int block_row = blockIdx.y * 128;
    const int block_col = blockIdx.x * 128;

    float d[2][8][4];
#pragma unroll
    for (int mt = 0; mt < 2; mt++)
#pragma unroll
        for (int nt = 0; nt < 8; nt++)
#pragma unroll
            for (int q = 0; q < 4; q++) d[mt][nt][q] = 0.f;

    auto issue = [&](int c, int s) {
        const float* asrc = (c < 4) ? input : g_agg;
        const int kofs = (c & 3) * 32;
        uint32_t abase = sbase + (s * STAGE_WORDS) * 4;
        uint32_t bbase = abase + MAT_WORDS * 4;
#pragma unroll
        for (int i = 0; i < 4; i++) {
            int f = i * 256 + tid, row = f >> 3, c4 = f & 7;
            bool p = (block_row + row) < M;
            cp16(abase + (row * PADW + c4 * 4) * 4,
                 asrc + (size_t)(block_row + row) * N_D + kofs + c4 * 4, p);
            cp16(bbase + (row * PADW + c4 * 4) * 4,
                 &g_W1t[(size_t)(block_col + row) * N_CAT + c * 32 + c4 * 4], true);
        }
    };

    issue(0, 0); CP_COMMIT();
    issue(1, 1); CP_COMMIT();

    for (int c = 0; c < 8; c++) {
        const int s = c & 1;
        CP_WAIT1();
        __syncthreads();
        const uint32_t* As = sm + s * STAGE_WORDS;
        const uint32_t* Bs = As + MAT_WORDS;
#pragma unroll
        for (int ks = 0; ks < 4; ks++) {
            uint32_t a[2][4], b[8][2];
            const int kc = ks * 8 + tig;
#pragma unroll
            for (int mt = 0; mt < 2; mt++) {
                int rb = warp_m * 32 + mt * 16 + grp;
                a[mt][0] = f2tf32(__uint_as_float(As[rb * PADW + kc]));
                a[mt][1] = f2tf32(__uint_as_float(As[(rb + 8) * PADW + kc]));
                a[mt][2] = f2tf32(__uint_as_float(As[rb * PADW + kc + 4]));
                a[mt][3] = f2tf32(__uint_as_float(As[(rb + 8) * PADW + kc + 4]));
            }
#pragma unroll
            for (int nt = 0; nt < 8; nt++) {
                int nb = warp_n * 64 + nt * 8 + grp;
                b[nt][0] = Bs[nb * PADW + kc];
                b[nt][1] = Bs[nb * PADW + kc + 4];
            }
#pragma unroll
            for (int mt = 0; mt < 2; mt++)
#pragma unroll
                for (int nt = 0; nt < 8; nt++) mma_tf32(d[mt][nt], a[mt], b[nt]);
        }
        __syncthreads();
        if (c + 2 < 8) issue(c + 2, s);
        CP_COMMIT();
    }

    // epilogue: +b1p, write g_h, accumulate column sum/sumsq
    float cs[16], cq[16];
#pragma unroll
    for (int i = 0; i < 16; i++) { cs[i] = 0.f; cq[i] = 0.f; }

#pragma unroll
    for (int mt = 0; mt < 2; mt++) {
        int r0 = block_row + warp_m * 32 + mt * 16 + grp;
#pragma unroll
        for (int nt = 0; nt < 8; nt++) {
            int col = block_col + warp_n * 64 + nt * 8 + tig * 2;
            float bx = g_b1p[col], by = g_b1p[col + 1];
            float vx = d[mt][nt][0] + bx, vy = d[mt][nt][1] + by;
            float vz = d[mt][nt][2] + bx, vw = d[mt][nt][3] + by;
            if (r0 < M) {
                *reinterpret_cast<float2*>(&g_h[(size_t)r0 * N_H + col]) = make_float2(vx, vy);
                cs[nt * 2]     += vx;  cq[nt * 2]     += vx * vx;
                cs[nt * 2 + 1] += vy;  cq[nt * 2 + 1] += vy * vy;
            }
            if (r0 + 8 < M) {
                *reinterpret_cast<float2*>(&g_h[(size_t)(r0 + 8) * N_H + col]) = make_float2(vz, vw);
                cs[nt * 2]     += vz;  cq[nt * 2]     += vz * vz;
                cs[nt * 2 + 1] += vw;  cq[nt * 2 + 1] += vw * vw;
            }
        }
    }
    // reduce over grp (lanes differ by bits 2..4), then atomics from grp==0 lanes
#pragma unroll
    for (int i = 0; i < 16; i++) {
        float s = cs[i], q = cq[i];
        s += __shfl_xor_sync(0xffffffffu, s, 4);
        s += __shfl_xor_sync(0xffffffffu, s, 8);
        s += __shfl_xor_sync(0xffffffffu, s, 16);
        q += __shfl_xor_sync(0xffffffffu, q, 4);
        q += __shfl_xor_sync(0xffffffffu, q, 8);
        q += __shfl_xor_sync(0xffffffffu, q, 16);
        if (grp == 0) {
            int col = block_col + warp_n * 64 + (i >> 1) * 8 + tig * 2 + (i & 1);
            atomicAdd(&g_stats[512 + col], s);
            atomicAdd(&g_stats[768 + col], q);
        }
    }
}

// GEMM2: out = relu(h*scale2+shift2) @ W2t^T + b2 ; BN2 params computed inline
__global__ __launch_bounds__(256, 2)
void k_gemm2_mma(const float* __restrict__ gamma2, const float* __restrict__ beta2,
                 const float* __restrict__ b2, float* __restrict__ out,
                 int M, float n_inv) {
    extern __shared__ uint32_t sm[];
    const uint32_t sbase = smem_u32(sm);
    float* scs = reinterpret_cast<float*>(sm + 2 * STAGE_WORDS);
    float* shs = scs + 256;
    const int tid = threadIdx.x, wid = tid >> 5, lane = tid & 31;
    const int warp_m = wid & 3, warp_n = wid >> 2;
    const int grp = lane >> 2, tig = lane & 3;
    const int block_row = blockIdx.y * 128;

    {
        float mean = g_stats[512 + tid] * n_inv;
        float var  = g_stats[768 + tid] * n_inv - mean * mean;
        float sc   = gamma2[tid] * rsqrtf(var + BN_EPS);
        scs[tid] = sc;
        shs[tid] = beta2[tid] - mean * sc;
    }

    float d[2][8][4];
#pragma unroll
    for (int mt = 0; mt < 2; mt++)
#pragma unroll
        for (int nt = 0; nt < 8; nt++)
#pragma unroll
            for (int q = 0; q < 4; q++) d[mt][nt][q] = 0.f;

    auto issue = [&](int c, int s) {
        uint32_t abase = sbase + (s * STAGE_WORDS) * 4;
        uint32_t bbase = abase + MAT_WORDS * 4;
#pragma unroll
        for (int i = 0; i < 4; i++) {
            int f = i * 256 + tid, row = f >> 3, c4 = f & 7;
            bool p = (block_row + row) < M;
            cp16(abase + (row * PADW + c4 * 4) * 4,
                 &g_h[(size_t)(block_row + row) * N_H + c * 32 + c4 * 4], p);
            cp16(bbase + (row * PADW + c4 * 4) * 4,
                 &g_W2t[(size_t)row * N_H + c * 32 + c4 * 4], true);
        }
    };

    issue(0, 0); CP_COMMIT();
    issue(1, 1); CP_COMMIT();
    __syncthreads();   // covers scs/shs fill

    for (int c = 0; c < 8; c++) {
        const int s = c & 1;
        CP_WAIT1();
        __syncthreads();
        const uint32_t* As = sm + s * STAGE_WORDS;
        const uint32_t* Bs = As + MAT_WORDS;
#pragma unroll
        for (int ks = 0; ks < 4; ks++) {
            uint32_t a[2][4], b[8][2];
            const int kc = ks * 8 + tig;
            const int k0 = c * 32 + kc, k1 = k0 + 4;
            const float sc0 = scs[k0], sh0 = shs[k0];
            const float sc1 = scs[k1], sh1 = shs[k1];
#pragma unroll
            for (int mt = 0; mt < 2; mt++) {
                int rb = warp_m * 32 + mt * 16 + grp;
                float v0 = __uint_as_float(As[rb * PADW + kc]);
                float v1 = __uint_as_float(As[(rb + 8) * PADW + kc]);
                float v2 = __uint_as_float(As[rb * PADW + kc + 4]);
                float v3 = __uint_as_float(As[(rb + 8) * PADW + kc + 4]);
                a[mt][0] = f2tf32(fmaxf(v0 * sc0 + sh0, 0.f));
                a[mt][1] = f2tf32(fmaxf(v1 * sc0 + sh0, 0.f));
                a[mt][2] = f2tf32(fmaxf(v2 * sc1 + sh1, 0.f));
                a[mt][3] = f2tf32(fmaxf(v3 * sc1 + sh1, 0.f));
            }
#pragma unroll
            for (int nt = 0; nt < 8; nt++) {
                int nb = warp_n * 64 + nt * 8 + grp;
                b[nt][0] = Bs[nb * PADW + kc];
                b[nt][1] = Bs[nb * PADW + kc + 4];
            }
#pragma unroll
            for (int mt = 0; mt < 2; mt++)
#pragma unroll
                for (int nt = 0; nt < 8; nt++) mma_tf32(d[mt][nt], a[mt], b[nt]);
        }
        __syncthreads();
        if (c + 2 < 8) issue(c + 2, s);
        CP_COMMIT();
    }

#pragma unroll
    for (int mt = 0; mt < 2; mt++) {
        int r0 = block_row + warp_m * 32 + mt * 16 + grp;
#pragma unroll
        for (int nt = 0; nt < 8; nt++) {
            int col = warp_n * 64 + nt * 8 + tig * 2;
            float bx = b2[col], by = b2[col + 1];
            if (r0 < M)
                *reinterpret_cast<float2*>(&out[(size_t)r0 * N_D + col]) =
                    make_float2(d[mt][nt][0] + bx, d[mt][nt][1] + by);
            if (r0 + 8 < M)
                *reinterpret_cast<float2*>(&out[(size_t)(r0 + 8) * N_D + col]) =
                    make_float2(d[mt][nt][2] + bx, d[mt][nt][3] + by);
        }
    }
}

// ---------------------------------------------------------------------------
// Launch
// ---------------------------------------------------------------------------
extern "C" void kernel_launch(void* const* d_in, const int* in_sizes, int n_in,
                              void* d_out, int out_size) {
    const float* input  = (const float*)d_in[0];
    const int*   rows   = (const int*)  d_in[1];
    const int*   cols   = (const int*)  d_in[2];
    const float* vals   = (const float*)d_in[3];
    const float* gamma1 = (const float*)d_in[4];
    const float* beta1  = (const float*)d_in[5];
    const float* W1     = (const float*)d_in[6];
    const float* b1     = (const float*)d_in[7];
    const float* gamma2 = (const float*)d_in[8];
    const float* beta2  = (const float*)d_in[9];
    const float* W2     = (const float*)d_in[10];
    const float* b2     = (const float*)d_in[11];
    float* out = (float*)d_out;

    const int n = in_sizes[0] / N_D;
    const int E = in_sizes[1];
    const float n_inv = 1.0f / (float)n;

    cudaFuncSetAttribute(k_gemm1_mma, cudaFuncAttributeMaxDynamicSharedMemorySize, PIPE_BYTES);
    cudaFuncSetAttribute(k_gemm2_mma, cudaFuncAttributeMaxDynamicSharedMemorySize, G2_SMEM);

    // 0: zero agg + stats
    {
        size_t n4 = (size_t)n * N_D / 4;
        k_zero<<<(int)((n4 + 255) / 256), 256>>>(n4);
    }
    // 1: stats of input half
    k_stats_input<<<512, 128>>>(input, n);
    // 2: W2 transpose/round
    k_w2prep<<<128, 256>>>(W2);
    // 3: SpMM (8 edges/warp)  <- ncu profile target
    {
        int warps = (E + 7) / 8;
        int blocks = (warps * 32 + 255) / 256;
        k_spmm<<<blocks, 256>>>(input, rows, cols, vals, E);
    }
    // 4: stats of agg half
    k_stats_agg<<<512, 128>>>(n);
    // 5: BN1 inline + fold into W1 + b1p
    k_w1prep<<<256, 256>>>(W1, b1, gamma1, beta1, n_inv);
    // 6: GEMM1 (+ fused h stats)
    {
        dim3 grid(2, (n + 127) / 128);
        k_gemm1_mma<<<grid, 256, PIPE_BYTES>>>(input, n);
    }
    // 7: GEMM2 (BN2 inline)
    {
        dim3 grid(1, (n + 127) / 128);
        k_gemm2_mma<<<grid, 256, G2_SMEM>>>(gamma2, beta2, b2, out, n, n_inv);
    }
}

// round 7
// speedup vs baseline: 2.8960x; 1.2008x over previous
#include <cuda_runtime.h>
#include <cstdint>
#include <cstddef>

#define N_D   128
#define N_H   256
#define N_CAT 256
#define BN_EPS 1e-5f
#define MAXN  100000

// ---------------------------------------------------------------------------
// Scratch
// ---------------------------------------------------------------------------
__device__ __align__(1024) float g_agg[(size_t)MAXN * N_D];   // 51.2 MB
__device__ __align__(1024) float g_h  [(size_t)MAXN * N_H];   // 102.4 MB
__device__ float g_stats[4 * 256];   // [0:256) sum_cat [256:512) sq_cat [512:768) sum_h [768:1024) sq_h
__device__ __align__(16) uint32_t g_W1t[N_H * N_CAT];  // [n][k] raw W1^T, tf32 bits
__device__ __align__(16) uint32_t g_W2t[N_D * N_H];    // [n][k] raw W2^T, tf32 bits

// ---------------------------------------------------------------------------
// Helpers
// ---------------------------------------------------------------------------
__device__ __forceinline__ uint32_t f2tf32(float x) {
    uint32_t r;
    asm("cvt.rna.tf32.f32 %0, %1;" : "=r"(r) : "f"(x));
    return r;
}
__device__ __forceinline__ uint32_t smem_u32(const void* p) {
    uint32_t a;
    asm("{ .reg .u64 t; cvta.to.shared.u64 t, %1; cvt.u32.u64 %0, t; }" : "=r"(a) : "l"(p));
    return a;
}
__device__ __forceinline__ void cp16(uint32_t dst, const void* src, bool pred) {
    int sz = pred ? 16 : 0;
    asm volatile("cp.async.cg.shared.global [%0], [%1], 16, %2;"
                 :: "r"(dst), "l"(src), "r"(sz) : "memory");
}
#define CP_COMMIT() asm volatile("cp.async.commit_group;" ::: "memory")
#define CP_WAIT1()  asm volatile("cp.async.wait_group 1;" ::: "memory")
__device__ __forceinline__ void mma_tf32(float d[4], const uint32_t a[4],
                                         const uint32_t b[2]) {
    asm volatile(
        "mma.sync.aligned.m16n8k8.row.col.f32.tf32.tf32.f32 "
        "{%0,%1,%2,%3}, {%4,%5,%6,%7}, {%8,%9}, {%0,%1,%2,%3};"
        : "+f"(d[0]), "+f"(d[1]), "+f"(d[2]), "+f"(d[3])
        : "r"(a[0]), "r"(a[1]), "r"(a[2]), "r"(a[3]), "r"(b[0]), "r"(b[1]));
}

// ---------------------------------------------------------------------------
// Launch 0: zero agg+stats, transpose/round W1 and W2
// ---------------------------------------------------------------------------
__global__ void k_zero_prep(size_t n4, const float* __restrict__ W1,
                            const float* __restrict__ W2) {
    size_t i = (size_t)blockIdx.x * blockDim.x + threadIdx.x;
    size_t stride = (size_t)gridDim.x * blockDim.x;
    float4* p = reinterpret_cast<float4*>(g_agg);
    float4 z = make_float4(0.f, 0.f, 0.f, 0.f);
    for (; i < n4; i += stride) p[i] = z;
    int j = blockIdx.x, t = threadIdx.x;
    if (j == 0)
        for (int q = t; q < 4 * 256; q += blockDim.x) g_stats[q] = 0.f;
    if (j < 256)
        g_W1t[(size_t)j * N_CAT + t] = f2tf32(W1[(size_t)t * N_H + j]);
    else if (j < 384)
        g_W2t[(size_t)(j - 256) * N_H + t] = f2tf32(W2[(size_t)t * N_D + (j - 256)]);
}

// Launch 1: SpMM, 8 edges/warp, batched gathers (MLP=8)
__global__ void k_spmm(const float* __restrict__ x, const int* __restrict__ rows,
                       const int* __restrict__ cols, const float* __restrict__ vals, int E) {
    int gw = (int)(((size_t)blockIdx.x * blockDim.x + threadIdx.x) >> 5);
    int lane = threadIdx.x & 31;
    int base = gw * 8;
    if (base >= E) return;

    int e = base + (lane & 7);
    bool ev = e < E;
    int c = ev ? cols[e] : 0;
    int r = ev ? rows[e] : 0;
    float v = ev ? vals[e] : 0.f;

    float4 m[8];
    int ri[8];
    float vi[8];
#pragma unroll
    for (int i = 0; i < 8; i++) {
        int ci = __shfl_sync(0xffffffffu, c, i);
        ri[i]  = __shfl_sync(0xffffffffu, r, i);
        vi[i]  = __shfl_sync(0xffffffffu, v, i);
        m[i] = reinterpret_cast<const float4*>(x + (size_t)ci * N_D)[lane];
    }
#pragma unroll
    for (int i = 0; i < 8; i++) {
        if (base + i < E) {
            float* dst = g_agg + (size_t)ri[i] * N_D + lane * 4;
            asm volatile("red.global.add.v4.f32 [%0], {%1,%2,%3,%4};"
                         :: "l"(dst), "f"(vi[i] * m[i].x), "f"(vi[i] * m[i].y),
                            "f"(vi[i] * m[i].z), "f"(vi[i] * m[i].w) : "memory");
        }
    }
}

// Launch 2: column stats of x_cat = [input | g_agg]
__global__ void k_stats_cat(const float* __restrict__ x, int n) {
    int t = threadIdx.x;   // 0..255
    const float* base = (t < N_D) ? (x + t) : (g_agg + (t - N_D));
    float s = 0.f, sq = 0.f;
    for (int r = blockIdx.x; r < n; r += gridDim.x) {
        float v = base[(size_t)r * N_D];
        s += v; sq += v * v;
    }
    atomicAdd(&g_stats[t], s);
    atomicAdd(&g_stats[256 + t], sq);
}

// ---------------------------------------------------------------------------
// GEMMs: mma.sync m16n8k8 tf32, CTA tile 128x128, 8 warps (4Mx2N),
// cp.async 2-stage pipeline.
// ---------------------------------------------------------------------------
#define PADW 36
#define MAT_WORDS (128 * PADW)
#define STAGE_WORDS (2 * MAT_WORDS)
#define PIPE_BYTES (2 * STAGE_WORDS * 4)       // 73728
#define G_SMEM (PIPE_BYTES + 512 * 4)

// Launch 3 (PROFILED): GEMM1.
// h = (sc1*x)@W1t^T + [sum_k sh1[k]W1t[:,k] + b1]; BN1 params inline from stats;
// shift-dot computed from B fragments; fused column stats of h.
__global__ __launch_bounds__(256, 2)
void k_gemm1_mma(const float* __restrict__ input,
                 const float* __restrict__ gamma1, const float* __restrict__ beta1,
                 const float* __restrict__ b1, int M, float n_inv) {
    extern __shared__ uint32_t sm[];
    const uint32_t sbase = smem_u32(sm);
    float* scs = reinterpret_cast<float*>(sm + 2 * STAGE_WORDS);
    float* shs = scs + 256;
    const int tid = threadIdx.x, wid = tid >> 5, lane = tid & 31;
    const int warp_m = wid & 3, warp_n = wid >> 2;
    const int grp = lane >> 2, tig = lane & 3;
    const int block_row = blockIdx.y * 128;
    const int block_col = blockIdx.x * 128;

    {   // BN1 params inline
        float mean = g_stats[tid] * n_inv;
        float var  = g_stats[256 + tid] * n_inv - mean * mean;
        float sc   = gamma1[tid] * rsqrtf(var + BN_EPS);
        scs[tid] = sc;
        shs[tid] = beta1[tid] - mean * sc;
    }

    float d[2][8][4];
    float bs[8];
#pragma unroll
    for (int nt = 0; nt < 8; nt++) {
        bs[nt] = 0.f;
#pragma unroll
        for (int mt = 0; mt < 2; mt++)
#pragma unroll
            for (int q = 0; q < 4; q++) d[mt][nt][q] = 0.f;
    }

    auto issue = [&](int c, int s) {
        const float* asrc = (c < 4) ? input : g_agg;
        const int kofs = (c & 3) * 32;
        uint32_t abase = sbase + (s * STAGE_WORDS) * 4;
        uint32_t bbase = abase + MAT_WORDS * 4;
#pragma unroll
        for (int i = 0; i < 4; i++) {
            int f = i * 256 + tid, row = f >> 3, c4 = f & 7;
            bool p = (block_row + row) < M;
            cp16(abase + (row * PADW + c4 * 4) * 4,
                 asrc + (size_t)(block_row + row) * N_D + kofs + c4 * 4, p);
            cp16(bbase + (row * PADW + c4 * 4) * 4,
                 &g_W1t[(size_t)(block_col + row) * N_CAT + c * 32 + c4 * 4], true);
        }
    };

    issue(0, 0); CP_COMMIT();
    issue(1, 1); CP_COMMIT();
    __syncthreads();   // covers scs/shs fill

    for (int c = 0; c < 8; c++) {
        const int s = c & 1;
        CP_WAIT1();
        __syncthreads();
        const uint32_t* As = sm + s * STAGE_WORDS;
        const uint32_t* Bs = As + MAT_WORDS;
#pragma unroll
        for (int ks = 0; ks < 4; ks++) {
            uint32_t a[2][4], b[8][2];
            const int kc = ks * 8 + tig;
            const int k0 = c * 32 + kc, k1 = k0 + 4;
            const float sc0 = scs[k0], sc1 = scs[k1];
            const float sh0 = shs[k0], sh1 = shs[k1];
#pragma unroll
            for (int mt = 0; mt < 2; mt++) {
                int rb = warp_m * 32 + mt * 16 + grp;
                a[mt][0] = f2tf32(__uint_as_float(As[rb * PADW + kc]) * sc0);
                a[mt][1] = f2tf32(__uint_as_float(As[(rb + 8) * PADW + kc]) * sc0);
                a[mt][2] = f2tf32(__uint_as_float(As[rb * PADW + kc + 4]) * sc1);
                a[mt][3] = f2tf32(__uint_as_float(As[(rb + 8) * PADW + kc + 4]) * sc1);
            }
#pragma unroll
            for (int nt = 0; nt < 8; nt++) {
                int nb = warp_n * 64 + nt * 8 + grp;
                b[nt][0] = Bs[nb * PADW + kc];
                b[nt][1] = Bs[nb * PADW + kc + 4];
                bs[nt] += sh0 * __uint_as_float(b[nt][0]) + sh1 * __uint_as_float(b[nt][1]);
            }
#pragma unroll
            for (int mt = 0; mt < 2; mt++)
#pragma unroll
                for (int nt = 0; nt < 8; nt++) mma_tf32(d[mt][nt], a[mt], b[nt]);
        }
        __syncthreads();
        if (c + 2 < 8) issue(c + 2, s);
        CP_COMMIT();
    }

    // shift-dot: reduce bs over tig lanes, then broadcast rows tig*2, tig*2+1
    float bxv[8], byv[8];
#pragma unroll
    for (int nt = 0; nt < 8; nt++) {
        float s = bs[nt];
        s += __shfl_xor_sync(0xffffffffu, s, 1);
        s += __shfl_xor_sync(0xffffffffu, s, 2);
        bxv[nt] = __shfl_sync(0xffffffffu, s, tig * 8);      // row nt*8 + tig*2
        byv[nt] = __shfl_sync(0xffffffffu, s, tig * 8 + 4);  // row nt*8 + tig*2+1
    }

    // epilogue: +shift-dot +b1, write g_h, accumulate column sum/sumsq
    float cs[16], cq[16];
#pragma unroll
    for (int i = 0; i < 16; i++) { cs[i] = 0.f; cq[i] = 0.f; }

#pragma unroll
    for (int mt = 0; mt < 2; mt++) {
        int r0 = block_row + warp_m * 32 + mt * 16 + grp;
#pragma unroll
        for (int nt = 0; nt < 8; nt++) {
            int col = block_col + warp_n * 64 + nt * 8 + tig * 2;
            float bx = b1[col] + bxv[nt], by = b1[col + 1] + byv[nt];
            float vx = d[mt][nt][0] + bx, vy = d[mt][nt][1] + by;
            float vz = d[mt][nt][2] + bx, vw = d[mt][nt][3] + by;
            if (r0 < M) {
                *reinterpret_cast<float2*>(&g_h[(size_t)r0 * N_H + col]) = make_float2(vx, vy);
                cs[nt * 2]     += vx;  cq[nt * 2]     += vx * vx;
                cs[nt * 2 + 1] += vy;  cq[nt * 2 + 1] += vy * vy;
            }
            if (r0 + 8 < M) {
                *reinterpret_cast<float2*>(&g_h[(size_t)(r0 + 8) * N_H + col]) = make_float2(vz, vw);
                cs[nt * 2]     += vz;  cq[nt * 2]     += vz * vz;
                cs[nt * 2 + 1] += vw;  cq[nt * 2 + 1] += vw * vw;
            }
        }
    }
#pragma unroll
    for (int i = 0; i < 16; i++) {
        float s = cs[i], q = cq[i];
        s += __shfl_xor_sync(0xffffffffu, s, 4);
        s += __shfl_xor_sync(0xffffffffu, s, 8);
        s += __shfl_xor_sync(0xffffffffu, s, 16);
        q += __shfl_xor_sync(0xffffffffu, q, 4);
        q += __shfl_xor_sync(0xffffffffu, q, 8);
        q += __shfl_xor_sync(0xffffffffu, q, 16);
        if (grp == 0) {
            int col = block_col + warp_n * 64 + (i >> 1) * 8 + tig * 2 + (i & 1);
            atomicAdd(&g_stats[512 + col], s);
            atomicAdd(&g_stats[768 + col], q);
        }
    }
}

// Launch 4: GEMM2: out = relu(h*sc2+sh2) @ W2t^T + b2 ; BN2 params inline
__global__ __launch_bounds__(256, 2)
void k_gemm2_mma(const float* __restrict__ gamma2, const float* __restrict__ beta2,
                 const float* __restrict__ b2, float* __restrict__ out,
                 int M, float n_inv) {
    extern __shared__ uint32_t sm[];
    const uint32_t sbase = smem_u32(sm);
    float* scs = reinterpret_cast<float*>(sm + 2 * STAGE_WORDS);
    float* shs = scs + 256;
    const int tid = threadIdx.x, wid = tid >> 5, lane = tid & 31;
    const int warp_m = wid & 3, warp_n = wid >> 2;
    const int grp = lane >> 2, tig = lane & 3;
    const int block_row = blockIdx.y * 128;

    {
        float mean = g_stats[512 + tid] * n_inv;
        float var  = g_stats[768 + tid] * n_inv - mean * mean;
        float sc   = gamma2[tid] * rsqrtf(var + BN_EPS);
        scs[tid] = sc;
        shs[tid] = beta2[tid] - mean * sc;
    }

    float d[2][8][4];
#pragma unroll
    for (int mt = 0; mt < 2; mt++)
#pragma unroll
        for (int nt = 0; nt < 8; nt++)
#pragma unroll
            for (int q = 0; q < 4; q++) d[mt][nt][q] = 0.f;

    auto issue = [&](int c, int s) {
        uint32_t abase = sbase + (s * STAGE_WORDS) * 4;
        uint32_t bbase = abase + MAT_WORDS * 4;
#pragma unroll
        for (int i = 0; i < 4; i++) {
            int f = i * 256 + tid, row = f >> 3, c4 = f & 7;
            bool p = (block_row + row) < M;
            cp16(abase + (row * PADW + c4 * 4) * 4,
                 &g_h[(size_t)(block_row + row) * N_H + c * 32 + c4 * 4], p);
            cp16(bbase + (row * PADW + c4 * 4) * 4,
                 &g_W2t[(size_t)row * N_H + c * 32 + c4 * 4], true);
        }
    };

    issue(0, 0); CP_COMMIT();
    issue(1, 1); CP_COMMIT();
    __syncthreads();

    for (int c = 0; c < 8; c++) {
        const int s = c & 1;
        CP_WAIT1();
        __syncthreads();
        const uint32_t* As = sm + s * STAGE_WORDS;
        const uint32_t* Bs = As + MAT_WORDS;
#pragma unroll
        for (int ks = 0; ks < 4; ks++) {
            uint32_t a[2][4], b[8][2];
            const int kc = ks * 8 + tig;
            const int k0 = c * 32 + kc, k1 = k0 + 4;
            const float sc0 = scs[k0], sh0 = shs[k0];
            const float sc1 = scs[k1], sh1 = shs[k1];
#pragma unroll
            for (int mt = 0; mt < 2; mt++) {
                int rb = warp_m * 32 + mt * 16 + grp;
                float v0 = __uint_as_float(As[rb * PADW + kc]);
                float v1 = __uint_as_float(As[(rb + 8) * PADW + kc]);
                float v2 = __uint_as_float(As[rb * PADW + kc + 4]);
                float v3 = __uint_as_float(As[(rb + 8) * PADW + kc + 4]);
                a[mt][0] = f2tf32(fmaxf(v0 * sc0 + sh0, 0.f));
                a[mt][1] = f2tf32(fmaxf(v1 * sc0 + sh0, 0.f));
                a[mt][2] = f2tf32(fmaxf(v2 * sc1 + sh1, 0.f));
                a[mt][3] = f2tf32(fmaxf(v3 * sc1 + sh1, 0.f));
            }
#pragma unroll
            for (int nt = 0; nt < 8; nt++) {
                int nb = warp_n * 64 + nt * 8 + grp;
                b[nt][0] = Bs[nb * PADW + kc];
                b[nt][1] = Bs[nb * PADW + kc + 4];
            }
#pragma unroll
            for (int mt = 0; mt < 2; mt++)
#pragma unroll
                for (int nt = 0; nt < 8; nt++) mma_tf32(d[mt][nt], a[mt], b[nt]);
        }
        __syncthreads();
        if (c + 2 < 8) issue(c + 2, s);
        CP_COMMIT();
    }

#pragma unroll
    for (int mt = 0; mt < 2; mt++) {
        int r0 = block_row + warp_m * 32 + mt * 16 + grp;
#pragma unroll
        for (int nt = 0; nt < 8; nt++) {
            int col = warp_n * 64 + nt * 8 + tig * 2;
            float bx = b2[col], by = b2[col + 1];
            if (r0 < M)
                *reinterpret_cast<float2*>(&out[(size_t)r0 * N_D + col]) =
                    make_float2(d[mt][nt][0] + bx, d[mt][nt][1] + by);
            if (r0 + 8 < M)
                *reinterpret_cast<float2*>(&out[(size_t)(r0 + 8) * N_D + col]) =
                    make_float2(d[mt][nt][2] + bx, d[mt][nt][3] + by);
        }
    }
}

// ---------------------------------------------------------------------------
// Launch
// ---------------------------------------------------------------------------
extern "C" void kernel_launch(void* const* d_in, const int* in_sizes, int n_in,
                              void* d_out, int out_size) {
    const float* input  = (const float*)d_in[0];
    const int*   rows   = (const int*)  d_in[1];
    const int*   cols   = (const int*)  d_in[2];
    const float* vals   = (const float*)d_in[3];
    const float* gamma1 = (const float*)d_in[4];
    const float* beta1  = (const float*)d_in[5];
    const float* W1     = (const float*)d_in[6];
    const float* b1     = (const float*)d_in[7];
    const float* gamma2 = (const float*)d_in[8];
    const float* beta2  = (const float*)d_in[9];
    const float* W2     = (const float*)d_in[10];
    const float* b2     = (const float*)d_in[11];
    float* out = (float*)d_out;

    const int n = in_sizes[0] / N_D;
    const int E = in_sizes[1];
    const float n_inv = 1.0f / (float)n;

    cudaFuncSetAttribute(k_gemm1_mma, cudaFuncAttributeMaxDynamicSharedMemorySize, G_SMEM);
    cudaFuncSetAttribute(k_gemm2_mma, cudaFuncAttributeMaxDynamicSharedMemorySize, G_SMEM);

    // 0: zero agg/stats + W transposes
    {
        size_t n4 = (size_t)n * N_D / 4;
        k_zero_prep<<<(int)((n4 + 255) / 256), 256>>>(n4, W1, W2);
    }
    // 1: SpMM
    {
        int warps = (E + 7) / 8;
        k_spmm<<<(warps * 32 + 255) / 256, 256>>>(input, rows, cols, vals, E);
    }
    // 2: stats of x_cat
    k_stats_cat<<<512, 256>>>(input, n);
    // 3: GEMM1 (BN1 inline, shift-dot fused, h-stats fused)  <- PROFILED
    {
        dim3 grid(2, (n + 127) / 128);
        k_gemm1_mma<<<grid, 256, G_SMEM>>>(input, gamma1, beta1, b1, n, n_inv);
    }
    // 4: GEMM2 (BN2 inline)
    {
        dim3 grid(1, (n + 127) / 128);
        k_gemm2_mma<<<grid, 256, G_SMEM>>>(gamma2, beta2, b2, out, n, n_inv);
    }
}

// round 8
// speedup vs baseline: 2.9234x; 1.0095x over previous
#include <cuda_runtime.h>
#include <cstdint>
#include <cstddef>

#define N_D   128
#define N_H   256
#define N_CAT 256
#define BN_EPS 1e-5f
#define MAXN  100000

// ---------------------------------------------------------------------------
// Scratch
// ---------------------------------------------------------------------------
__device__ __align__(1024) float g_agg[(size_t)MAXN * N_D];   // 51.2 MB
__device__ __align__(1024) float g_h  [(size_t)MAXN * N_H];   // 102.4 MB
__device__ float g_stats[4 * 256];   // [0:256) sum_cat [256:512) sq_cat [512:768) sum_h [768:1024) sq_h
__device__ __align__(16) uint32_t g_W1t[N_H * N_CAT];  // [n][k]: raw f32 bits, then BN1-folded tf32
__device__ __align__(16) uint32_t g_W2t[N_D * N_H];    // [n][k]: tf32 bits
__device__ float g_b1p[N_H];

// ---------------------------------------------------------------------------
// Helpers
// ---------------------------------------------------------------------------
__device__ __forceinline__ uint32_t f2tf32(float x) {
    uint32_t r;
    asm("cvt.rna.tf32.f32 %0, %1;" : "=r"(r) : "f"(x));
    return r;
}
__device__ __forceinline__ uint32_t smem_u32(const void* p) {
    uint32_t a;
    asm("{ .reg .u64 t; cvta.to.shared.u64 t, %1; cvt.u32.u64 %0, t; }" : "=r"(a) : "l"(p));
    return a;
}
__device__ __forceinline__ void cp16(uint32_t dst, const void* src, bool pred) {
    int sz = pred ? 16 : 0;
    asm volatile("cp.async.cg.shared.global [%0], [%1], 16, %2;"
                 :: "r"(dst), "l"(src), "r"(sz) : "memory");
}
#define CP_COMMIT() asm volatile("cp.async.commit_group;" ::: "memory")
#define CP_WAIT1()  asm volatile("cp.async.wait_group 1;" ::: "memory")
__device__ __forceinline__ void mma_tf32(float d[4], const uint32_t a[4],
                                         const uint32_t b[2]) {
    asm volatile(
        "mma.sync.aligned.m16n8k8.row.col.f32.tf32.tf32.f32 "
        "{%0,%1,%2,%3}, {%4,%5,%6,%7}, {%8,%9}, {%0,%1,%2,%3};"
        : "+f"(d[0]), "+f"(d[1]), "+f"(d[2]), "+f"(d[3])
        : "r"(a[0]), "r"(a[1]), "r"(a[2]), "r"(a[3]), "r"(b[0]), "r"(b[1]));
}

// ---------------------------------------------------------------------------
// Launch 0: zero agg+stats, transpose W1 (raw) and W2 (tf32)
// ---------------------------------------------------------------------------
__global__ void k_zero_prep(size_t n4, const float* __restrict__ W1,
                            const float* __restrict__ W2) {
    size_t i = (size_t)blockIdx.x * blockDim.x + threadIdx.x;
    size_t stride = (size_t)gridDim.x * blockDim.x;
    float4* p = reinterpret_cast<float4*>(g_agg);
    float4 z = make_float4(0.f, 0.f, 0.f, 0.f);
    for (; i < n4; i += stride) p[i] = z;
    int j = blockIdx.x, t = threadIdx.x;
    if (j == 0)
        for (int q = t; q < 4 * 256; q += blockDim.x) g_stats[q] = 0.f;
    if (j < 256)
        g_W1t[(size_t)j * N_CAT + t] = __float_as_uint(W1[(size_t)t * N_H + j]);
    else if (j < 384)
        g_W2t[(size_t)(j - 256) * N_H + t] = f2tf32(W2[(size_t)t * N_D + (j - 256)]);
}

// Launch 1: SpMM, 8 edges/warp, batched gathers (MLP=8)
__global__ void k_spmm(const float* __restrict__ x, const int* __restrict__ rows,
                       const int* __restrict__ cols, const float* __restrict__ vals, int E) {
    int gw = (int)(((size_t)blockIdx.x * blockDim.x + threadIdx.x) >> 5);
    int lane = threadIdx.x & 31;
    int base = gw * 8;
    if (base >= E) return;

    int e = base + (lane & 7);
    bool ev = e < E;
    int c = ev ? cols[e] : 0;
    int r = ev ? rows[e] : 0;
    float v = ev ? vals[e] : 0.f;

    float4 m[8];
    int ri[8];
    float vi[8];
#pragma unroll
    for (int i = 0; i < 8; i++) {
        int ci = __shfl_sync(0xffffffffu, c, i);
        ri[i]  = __shfl_sync(0xffffffffu, r, i);
        vi[i]  = __shfl_sync(0xffffffffu, v, i);
        m[i] = reinterpret_cast<const float4*>(x + (size_t)ci * N_D)[lane];
    }
#pragma unroll
    for (int i = 0; i < 8; i++) {
        if (base + i < E) {
            float* dst = g_agg + (size_t)ri[i] * N_D + lane * 4;
            asm volatile("red.global.add.v4.f32 [%0], {%1,%2,%3,%4};"
                         :: "l"(dst), "f"(vi[i] * m[i].x), "f"(vi[i] * m[i].y),
                            "f"(vi[i] * m[i].z), "f"(vi[i] * m[i].w) : "memory");
        }
    }
}

// Launch 2: column stats of x_cat = [input | g_agg]
__global__ void k_stats_cat(const float* __restrict__ x, int n) {
    int t = threadIdx.x;   // 0..255
    const float* base = (t < N_D) ? (x + t) : (g_agg + (t - N_D));
    float s = 0.f, sq = 0.f;
    for (int r = blockIdx.x; r < n; r += gridDim.x) {
        float v = base[(size_t)r * N_D];
        s += v; sq += v * v;
    }
    atomicAdd(&g_stats[t], s);
    atomicAdd(&g_stats[256 + t], sq);
}

// Launch 3: fold BN1 into W1t (raw->scaled tf32 in place) + b1p
__global__ void k_bnfold(const float* __restrict__ gamma1, const float* __restrict__ beta1,
                         const float* __restrict__ b1, float n_inv) {
    __shared__ float red[256];
    int j = blockIdx.x, t = threadIdx.x;
    float mean = g_stats[t] * n_inv;
    float var  = g_stats[256 + t] * n_inv - mean * mean;
    float sc   = gamma1[t] * rsqrtf(var + BN_EPS);
    float sh   = beta1[t] - mean * sc;
    float w = __uint_as_float(g_W1t[(size_t)j * N_CAT + t]);
    g_W1t[(size_t)j * N_CAT + t] = f2tf32(sc * w);
    red[t] = sh * w;
    __syncthreads();
    for (int s = 128; s > 0; s >>= 1) {
        if (t < s) red[t] += red[t + s];
        __syncthreads();
    }
    if (t == 0) g_b1p[j] = b1[j] + red[0];
}

// ---------------------------------------------------------------------------
// GEMMs: mma.sync m16n8k8 tf32. CTA tile 64x128, 128 threads = 4 warps (2Mx2N),
// warp tile 32x64. cp.async 2-stage pipeline, K chunks of 32.
// ---------------------------------------------------------------------------
#define PADW 36
#define A_WORDS (64 * PADW)                    // 2304
#define B_WORDS (128 * PADW)                   // 4608
#define STG_WORDS (A_WORDS + B_WORDS)          // 6912
#define PIPE_BYTES (2 * STG_WORDS * 4)         // 55296
#define G2_SMEM (PIPE_BYTES + 512 * 4)         // 57344

// Launch 4: GEMM1: h = A_folded @ W1t^T + b1p ; fused column stats of h
__global__ __launch_bounds__(128, 4)
void k_gemm1_mma(const float* __restrict__ input, int M) {
    extern __shared__ uint32_t sm[];
    const uint32_t sbase = smem_u32(sm);
    const int tid = threadIdx.x, wid = tid >> 5, lane = tid & 31;
    const int warp_m = wid & 1, warp_n = wid >> 1;
    const int grp = lane >> 2, tig = lane & 3;
    const int block_row = blockIdx.y * 64;
    const int block_col = blockIdx.x * 128;

    float d[2][8][4];
#pragma unroll
    for (int mt = 0; mt < 2; mt++)
#pragma unroll
        for (int nt = 0; nt < 8; nt++)
#pragma unroll
            for (int q = 0; q < 4; q++) d[mt][nt][q] = 0.f;

    auto issue = [&](int c, int s) {
        const float* asrc = (c < 4) ? input : g_agg;
        const int kofs = (c & 3) * 32;
        uint32_t abase = sbase + (s * STG_WORDS) * 4;
        uint32_t bbase = abase + A_WORDS * 4;
#pragma unroll
        for (int i = 0; i < 4; i++) {   // A: 64x32 = 512 float4
            int f = i * 128 + tid, row = f >> 3, c4 = f & 7;
            bool p = (block_row + row) < M;
            cp16(abase + (row * PADW + c4 * 4) * 4,
                 asrc + (size_t)(block_row + row) * N_D + kofs + c4 * 4, p);
        }
#pragma unroll
        for (int i = 0; i < 8; i++) {   // B: 128x32 = 1024 float4
            int f = i * 128 + tid, row = f >> 3, c4 = f & 7;
            cp16(bbase + (row * PADW + c4 * 4) * 4,
                 &g_W1t[(size_t)(block_col + row) * N_CAT + c * 32 + c4 * 4], true);
        }
    };

    issue(0, 0); CP_COMMIT();
    issue(1, 1); CP_COMMIT();

    for (int c = 0; c < 8; c++) {
        const int s = c & 1;
        CP_WAIT1();
        __syncthreads();
        const uint32_t* As = sm + s * STG_WORDS;
        const uint32_t* Bs = As + A_WORDS;
#pragma unroll
        for (int ks = 0; ks < 4; ks++) {
            uint32_t a[2][4], b[8][2];
            const int kc = ks * 8 + tig;
#pragma unroll
            for (int mt = 0; mt < 2; mt++) {
                int rb = warp_m * 32 + mt * 16 + grp;
                a[mt][0] = f2tf32(__uint_as_float(As[rb * PADW + kc]));
                a[mt][1] = f2tf32(__uint_as_float(As[(rb + 8) * PADW + kc]));
                a[mt][2] = f2tf32(__uint_as_float(As[rb * PADW + kc + 4]));
                a[mt][3] = f2tf32(__uint_as_float(As[(rb + 8) * PADW + kc + 4]));
            }
#pragma unroll
            for (int nt = 0; nt < 8; nt++) {
                int nb = warp_n * 64 + nt * 8 + grp;
                b[nt][0] = Bs[nb * PADW + kc];
                b[nt][1] = Bs[nb * PADW + kc + 4];
            }
#pragma unroll
            for (int mt = 0; mt < 2; mt++)
#pragma unroll
                for (int nt = 0; nt < 8; nt++) mma_tf32(d[mt][nt], a[mt], b[nt]);
        }
        __syncthreads();
        if (c + 2 < 8) issue(c + 2, s);
        CP_COMMIT();
    }

    // epilogue: +b1p, write g_h, accumulate column sum/sumsq
    float cs[16], cq[16];
#pragma unroll
    for (int i = 0; i < 16; i++) { cs[i] = 0.f; cq[i] = 0.f; }

#pragma unroll
    for (int mt = 0; mt < 2; mt++) {
        int r0 = block_row + warp_m * 32 + mt * 16 + grp;
#pragma unroll
        for (int nt = 0; nt < 8; nt++) {
            int col = block_col + warp_n * 64 + nt * 8 + tig * 2;
            float bx = g_b1p[col], by = g_b1p[col + 1];
            float vx = d[mt][nt][0] + bx, vy = d[mt][nt][1] + by;
            float vz = d[mt][nt][2] + bx, vw = d[mt][nt][3] + by;
            if (r0 < M) {
                *reinterpret_cast<float2*>(&g_h[(size_t)r0 * N_H + col]) = make_float2(vx, vy);
                cs[nt * 2]     += vx;  cq[nt * 2]     += vx * vx;
                cs[nt * 2 + 1] += vy;  cq[nt * 2 + 1] += vy * vy;
            }
            if (r0 + 8 < M) {
                *reinterpret_cast<float2*>(&g_h[(size_t)(r0 + 8) * N_H + col]) = make_float2(vz, vw);
                cs[nt * 2]     += vz;  cq[nt * 2]     += vz * vz;
                cs[nt * 2 + 1] += vw;  cq[nt * 2 + 1] += vw * vw;
            }
        }
    }
#pragma unroll
    for (int i = 0; i < 16; i++) {
        float s = cs[i], q = cq[i];
        s += __shfl_xor_sync(0xffffffffu, s, 4);
        s += __shfl_xor_sync(0xffffffffu, s, 8);
        s += __shfl_xor_sync(0xffffffffu, s, 16);
        q += __shfl_xor_sync(0xffffffffu, q, 4);
        q += __shfl_xor_sync(0xffffffffu, q, 8);
        q += __shfl_xor_sync(0xffffffffu, q, 16);
        if (grp == 0) {
            int col = block_col + warp_n * 64 + (i >> 1) * 8 + tig * 2 + (i & 1);
            atomicAdd(&g_stats[512 + col], s);
            atomicAdd(&g_stats[768 + col], q);
        }
    }
}

// Launch 5: GEMM2: out = relu(h*sc2+sh2) @ W2t^T + b2 ; BN2 params inline
__global__ __launch_bounds__(128, 4)
void k_gemm2_mma(const float* __restrict__ gamma2, const float* __restrict__ beta2,
                 const float* __restrict__ b2, float* __restrict__ out,
                 int M, float n_inv) {
    extern __shared__ uint32_t sm[];
    const uint32_t sbase = smem_u32(sm);
    float* scs = reinterpret_cast<float*>(sm + 2 * STG_WORDS);
    float* shs = scs + 256;
    const int tid = threadIdx.x, wid = tid >> 5, lane = tid & 31;
    const int warp_m = wid & 1, warp_n = wid >> 1;
    const int grp = lane >> 2, tig = lane & 3;
    const int block_row = blockIdx.y * 64;

    for (int k = tid; k < 256; k += 128) {
        float mean = g_stats[512 + k] * n_inv;
        float var  = g_stats[768 + k] * n_inv - mean * mean;
        float sc   = gamma2[k] * rsqrtf(var + BN_EPS);
        scs[k] = sc;
        shs[k] = beta2[k] - mean * sc;
    }

    float d[2][8][4];
#pragma unroll
    for (int mt = 0; mt < 2; mt++)
#pragma unroll
        for (int nt = 0; nt < 8; nt++)
#pragma unroll
            for (int q = 0; q < 4; q++) d[mt][nt][q] = 0.f;

    auto issue = [&](int c, int s) {
        uint32_t abase = sbase + (s * STG_WORDS) * 4;
        uint32_t bbase = abase + A_WORDS * 4;
#pragma unroll
        for (int i = 0; i < 4; i++) {
            int f = i * 128 + tid, row = f >> 3, c4 = f & 7;
            bool p = (block_row + row) < M;
            cp16(abase + (row * PADW + c4 * 4) * 4,
                 &g_h[(size_t)(block_row + row) * N_H + c * 32 + c4 * 4], p);
        }
#pragma unroll
        for (int i = 0; i < 8; i++) {
            int f = i * 128 + tid, row = f >> 3, c4 = f & 7;
            cp16(bbase + (row * PADW + c4 * 4) * 4,
                 &g_W2t[(size_t)row * N_H + c * 32 + c4 * 4], true);
        }
    };

    issue(0, 0); CP_COMMIT();
    issue(1, 1); CP_COMMIT();
    __syncthreads();   // covers scs/shs fill

    for (int c = 0; c < 8; c++) {
        const int s = c & 1;
        CP_WAIT1();
        __syncthreads();
        const uint32_t* As = sm + s * STG_WORDS;
        const uint32_t* Bs = As + A_WORDS;
#pragma unroll
        for (int ks = 0; ks < 4; ks++) {
            uint32_t a[2][4], b[8][2];
            const int kc = ks * 8 + tig;
            const int k0 = c * 32 + kc, k1 = k0 + 4;
            const float sc0 = scs[k0], sh0 = shs[k0];
            const float sc1 = scs[k1], sh1 = shs[k1];
#pragma unroll
            for (int mt = 0; mt < 2; mt++) {
                int rb = warp_m * 32 + mt * 16 + grp;
                float v0 = __uint_as_float(As[rb * PADW + kc]);
                float v1 = __uint_as_float(As[(rb + 8) * PADW + kc]);
                float v2 = __uint_as_float(As[rb * PADW + kc + 4]);
                float v3 = __uint_as_float(As[(rb + 8) * PADW + kc + 4]);
                a[mt][0] = f2tf32(fmaxf(v0 * sc0 + sh0, 0.f));
                a[mt][1] = f2tf32(fmaxf(v1 * sc0 + sh0, 0.f));
                a[mt][2] = f2tf32(fmaxf(v2 * sc1 + sh1, 0.f));
                a[mt][3] = f2tf32(fmaxf(v3 * sc1 + sh1, 0.f));
            }
#pragma unroll
            for (int nt = 0; nt < 8; nt++) {
                int nb = warp_n * 64 + nt * 8 + grp;
                b[nt][0] = Bs[nb * PADW + kc];
                b[nt][1] = Bs[nb * PADW + kc + 4];
            }
#pragma unroll
            for (int mt = 0; mt < 2; mt++)
#pragma unroll
                for (int nt = 0; nt < 8; nt++) mma_tf32(d[mt][nt], a[mt], b[nt]);
        }
        __syncthreads();
        if (c + 2 < 8) issue(c + 2, s);
        CP_COMMIT();
    }

#pragma unroll
    for (int mt = 0; mt < 2; mt++) {
        int r0 = block_row + warp_m * 32 + mt * 16 + grp;
#pragma unroll
        for (int nt = 0; nt < 8; nt++) {
            int col = warp_n * 64 + nt * 8 + tig * 2;
            float bx = b2[col], by = b2[col + 1];
            if (r0 < M)
                *reinterpret_cast<float2*>(&out[(size_t)r0 * N_D + col]) =
                    make_float2(d[mt][nt][0] + bx, d[mt][nt][1] + by);
            if (r0 + 8 < M)
                *reinterpret_cast<float2*>(&out[(size_t)(r0 + 8) * N_D + col]) =
                    make_float2(d[mt][nt][2] + bx, d[mt][nt][3] + by);
        }
    }
}

// ---------------------------------------------------------------------------
// Launch
// ---------------------------------------------------------------------------
extern "C" void kernel_launch(void* const* d_in, const int* in_sizes, int n_in,
                              void* d_out, int out_size) {
    const float* input  = (const float*)d_in[0];
    const int*   rows   = (const int*)  d_in[1];
    const int*   cols   = (const int*)  d_in[2];
    const float* vals   = (const float*)d_in[3];
    const float* gamma1 = (const float*)d_in[4];
    const float* beta1  = (const float*)d_in[5];
    const float* W1     = (const float*)d_in[6];
    const float* b1     = (const float*)d_in[7];
    const float* gamma2 = (const float*)d_in[8];
    const float* beta2  = (const float*)d_in[9];
    const float* W2     = (const float*)d_in[10];
    const float* b2     = (const float*)d_in[11];
    float* out = (float*)d_out;

    const int n = in_sizes[0] / N_D;
    const int E = in_sizes[1];
    const float n_inv = 1.0f / (float)n;

    cudaFuncSetAttribute(k_gemm1_mma, cudaFuncAttributeMaxDynamicSharedMemorySize, PIPE_BYTES);
    cudaFuncSetAttribute(k_gemm2_mma, cudaFuncAttributeMaxDynamicSharedMemorySize, G2_SMEM);

    // 0: zero agg/stats + W transposes
    {
        size_t n4 = (size_t)n * N_D / 4;
        k_zero_prep<<<(int)((n4 + 255) / 256), 256>>>(n4, W1, W2);
    }
    // 1: SpMM
    {
        int warps = (E + 7) / 8;
        k_spmm<<<(warps * 32 + 255) / 256, 256>>>(input, rows, cols, vals, E);
    }
    // 2: stats of x_cat
    k_stats_cat<<<512, 256>>>(input, n);
    // 3: BN1 fold into W1t + b1p
    k_bnfold<<<256, 256>>>(gamma1, beta1, b1, n_inv);
    // 4: GEMM1 (64x128 tiles, fused h-stats)
    {
        dim3 grid(2, (n + 63) / 64);
        k_gemm1_mma<<<grid, 128, PIPE_BYTES>>>(input, n);
    }
    // 5: GEMM2 (BN2 inline)
    {
        dim3 grid(1, (n + 63) / 64);
        k_gemm2_mma<<<grid, 128, G2_SMEM>>>(gamma2, beta2, b2, out, n, n_inv);
    }
}